// round 1
// baseline (speedup 1.0000x reference)
#include <cuda_runtime.h>

#define N_NODES 50000
#define N_EDGES 800000
#define D 128
#define BM 64
#define TM 4
#define TN 8

// ---------------- scratch (no allocations allowed) ----------------
__device__ float g_hneigh[(size_t)N_NODES * D];
__device__ float g_hbuf0[(size_t)N_NODES * D];
__device__ float g_hbuf1[(size_t)N_NODES * D];
__device__ float g_deg[N_NODES];
__device__ float g_invdeg[N_NODES];

// ---------------- degree ----------------
__global__ void deg_kernel(const int* __restrict__ dst) {
    int i = blockIdx.x * blockDim.x + threadIdx.x;
    int stride = gridDim.x * blockDim.x;
    for (int e = i; e < N_EDGES; e += stride)
        atomicAdd(&g_deg[dst[e]], 1.0f);
}

__global__ void invdeg_kernel() {
    int i = blockIdx.x * blockDim.x + threadIdx.x;
    if (i < N_NODES) g_invdeg[i] = 1.0f / fmaxf(g_deg[i], 1.0f);
}

// ---------------- edge scatter: one warp per edge ----------------
__global__ void scatter_kernel(const float* __restrict__ h,
                               const int* __restrict__ src,
                               const int* __restrict__ dst,
                               float* __restrict__ hneigh) {
    int warp = (blockIdx.x * blockDim.x + threadIdx.x) >> 5;
    int lane = threadIdx.x & 31;
    int nwarps = (gridDim.x * blockDim.x) >> 5;
    for (int e = warp; e < N_EDGES; e += nwarps) {
        int s = src[e];
        int d = dst[e];
        float4 v = reinterpret_cast<const float4*>(h + (size_t)s * D)[lane];
        float* p = hneigh + (size_t)d * D + lane * 4;
        atomicAdd(p + 0, v.x);
        atomicAdd(p + 1, v.y);
        atomicAdd(p + 2, v.z);
        atomicAdd(p + 3, v.w);
    }
}

// ---------------- fused dual GEMM: out = h@Ws + (hneigh*invdeg)@Wn + b, opt relu
// block: 256 threads (16x16), tile 64 nodes x 128 cols, 4x8 register tile.
// Both weight matrices staged fully in SMEM; h tiles staged with +1 pad.
__global__ void __launch_bounds__(256, 1)
gemm_kernel(const float* __restrict__ h,
            const float* __restrict__ hneigh,
            const float* __restrict__ Wself,
            const float* __restrict__ Wneigh,
            const float* __restrict__ bias,
            float* __restrict__ out, int relu) {
    extern __shared__ float smem[];
    float* sWs = smem;                       // D*D
    float* sWn = sWs + D * D;                // D*D
    float* sh  = sWn + D * D;                // BM*(D+1)
    float* sn  = sh + BM * (D + 1);          // BM*(D+1)

    const int tid = threadIdx.x;
    const int tx = tid & 15;                 // 16 column groups
    const int ty = tid >> 4;                 // 16 row groups
    const int m0 = blockIdx.x * BM;

    // stage weights (float4, coalesced)
    #pragma unroll 4
    for (int i = tid; i < D * D / 4; i += 256) {
        reinterpret_cast<float4*>(sWs)[i] = reinterpret_cast<const float4*>(Wself)[i];
        reinterpret_cast<float4*>(sWn)[i] = reinterpret_cast<const float4*>(Wneigh)[i];
    }
    // stage h / scaled-hneigh tiles
    for (int i = tid; i < BM * D; i += 256) {
        int m = i >> 7;            // i / 128
        int k = i & 127;           // i % 128
        int gm = m0 + m;
        float hv = 0.f, nv = 0.f;
        if (gm < N_NODES) {
            hv = h[(size_t)gm * D + k];
            nv = hneigh[(size_t)gm * D + k] * g_invdeg[gm];
        }
        sh[m * (D + 1) + k] = hv;
        sn[m * (D + 1) + k] = nv;
    }
    __syncthreads();

    float acc[TM][TN];
    #pragma unroll
    for (int i = 0; i < TM; i++)
        #pragma unroll
        for (int j = 0; j < TN; j++) acc[i][j] = 0.f;

    const int mbase = ty * TM;
    const int jbase = tx * TN;

    // self pass
    #pragma unroll 8
    for (int k = 0; k < D; ++k) {
        float4 w0 = *reinterpret_cast<const float4*>(sWs + k * D + jbase);
        float4 w1 = *reinterpret_cast<const float4*>(sWs + k * D + jbase + 4);
        #pragma unroll
        for (int i = 0; i < TM; i++) {
            float a = sh[(mbase + i) * (D + 1) + k];
            acc[i][0] += a * w0.x; acc[i][1] += a * w0.y;
            acc[i][2] += a * w0.z; acc[i][3] += a * w0.w;
            acc[i][4] += a * w1.x; acc[i][5] += a * w1.y;
            acc[i][6] += a * w1.z; acc[i][7] += a * w1.w;
        }
    }
    // neighbor pass
    #pragma unroll 8
    for (int k = 0; k < D; ++k) {
        float4 w0 = *reinterpret_cast<const float4*>(sWn + k * D + jbase);
        float4 w1 = *reinterpret_cast<const float4*>(sWn + k * D + jbase + 4);
        #pragma unroll
        for (int i = 0; i < TM; i++) {
            float a = sn[(mbase + i) * (D + 1) + k];
            acc[i][0] += a * w0.x; acc[i][1] += a * w0.y;
            acc[i][2] += a * w0.z; acc[i][3] += a * w0.w;
            acc[i][4] += a * w1.x; acc[i][5] += a * w1.y;
            acc[i][6] += a * w1.z; acc[i][7] += a * w1.w;
        }
    }

    // epilogue: bias + optional relu
    #pragma unroll
    for (int i = 0; i < TM; i++) {
        int gm = m0 + mbase + i;
        if (gm >= N_NODES) continue;
        float4 o0, o1;
        o0.x = acc[i][0] + bias[jbase + 0];
        o0.y = acc[i][1] + bias[jbase + 1];
        o0.z = acc[i][2] + bias[jbase + 2];
        o0.w = acc[i][3] + bias[jbase + 3];
        o1.x = acc[i][4] + bias[jbase + 4];
        o1.y = acc[i][5] + bias[jbase + 5];
        o1.z = acc[i][6] + bias[jbase + 6];
        o1.w = acc[i][7] + bias[jbase + 7];
        if (relu) {
            o0.x = fmaxf(o0.x, 0.f); o0.y = fmaxf(o0.y, 0.f);
            o0.z = fmaxf(o0.z, 0.f); o0.w = fmaxf(o0.w, 0.f);
            o1.x = fmaxf(o1.x, 0.f); o1.y = fmaxf(o1.y, 0.f);
            o1.z = fmaxf(o1.z, 0.f); o1.w = fmaxf(o1.w, 0.f);
        }
        float4* po = reinterpret_cast<float4*>(out + (size_t)gm * D + jbase);
        po[0] = o0;
        po[1] = o1;
    }
}

// ---------------- launch ----------------
extern "C" void kernel_launch(void* const* d_in, const int* in_sizes, int n_in,
                              void* d_out, int out_size) {
    const float* features = (const float*)d_in[0];
    const int* src = (const int*)d_in[1];
    const int* dst = (const int*)d_in[2];
    const float* Ws[3] = {(const float*)d_in[3], (const float*)d_in[6], (const float*)d_in[9]};
    const float* Wn[3] = {(const float*)d_in[4], (const float*)d_in[7], (const float*)d_in[10]};
    const float* bb[3] = {(const float*)d_in[5], (const float*)d_in[8], (const float*)d_in[11]};
    float* out = (float*)d_out;

    void *p_hneigh, *p_h0, *p_h1, *p_deg;
    cudaGetSymbolAddress(&p_hneigh, g_hneigh);
    cudaGetSymbolAddress(&p_h0, g_hbuf0);
    cudaGetSymbolAddress(&p_h1, g_hbuf1);
    cudaGetSymbolAddress(&p_deg, g_deg);

    size_t smem_bytes = (size_t)(2 * D * D + 2 * BM * (D + 1)) * sizeof(float);
    cudaFuncSetAttribute(gemm_kernel, cudaFuncAttributeMaxDynamicSharedMemorySize,
                         (int)smem_bytes);

    // degree (identical across layers): exact integer-valued float sums
    cudaMemsetAsync(p_deg, 0, N_NODES * sizeof(float));
    deg_kernel<<<1024, 256>>>(dst);
    invdeg_kernel<<<(N_NODES + 255) / 256, 256>>>();

    const float* hin = features;
    float* bufs[3] = {(float*)p_h0, (float*)p_h1, out};
    for (int l = 0; l < 3; ++l) {
        cudaMemsetAsync(p_hneigh, 0, (size_t)N_NODES * D * sizeof(float));
        scatter_kernel<<<2048, 256>>>(hin, src, dst, (float*)p_hneigh);
        gemm_kernel<<<(N_NODES + BM - 1) / BM, 256, smem_bytes>>>(
            hin, (float*)p_hneigh, Ws[l], Wn[l], bb[l], bufs[l], (l < 2) ? 1 : 0);
        hin = bufs[l];
    }
}

// round 2
// speedup vs baseline: 2.6232x; 2.6232x over previous
#include <cuda_runtime.h>

#define N_NODES 50000
#define N_EDGES 800000
#define D 128
#define GBM 128
#define GBK 32

// ---------------- scratch (no allocations allowed) ----------------
__device__ float g_hneigh[(size_t)N_NODES * D];
__device__ float g_hbuf0[(size_t)N_NODES * D];
__device__ float g_hbuf1[(size_t)N_NODES * D];
__device__ int g_hist[N_NODES];
__device__ int g_cursor[N_NODES];
__device__ int g_rowstart[N_NODES + 1];
__device__ int g_col[N_EDGES];

// ---------------- CSR build ----------------
__global__ void hist_kernel(const int* __restrict__ dst) {
    int e = blockIdx.x * blockDim.x + threadIdx.x;
    if (e < N_EDGES) atomicAdd(&g_hist[dst[e]], 1);
}

__global__ void scan_kernel() {
    // single block, 1024 threads: blocked exclusive scan of g_hist -> g_rowstart/g_cursor
    __shared__ int psum[1024];
    const int CH = (N_NODES + 1023) / 1024;  // 49
    int t = threadIdx.x;
    int base = t * CH;
    int s = 0;
    for (int i = 0; i < CH; i++) {
        int idx = base + i;
        if (idx < N_NODES) s += g_hist[idx];
    }
    psum[t] = s;
    __syncthreads();
    // Hillis-Steele inclusive scan
    for (int off = 1; off < 1024; off <<= 1) {
        int v = psum[t];
        int add = (t >= off) ? psum[t - off] : 0;
        __syncthreads();
        psum[t] = v + add;
        __syncthreads();
    }
    int run = (t == 0) ? 0 : psum[t - 1];
    for (int i = 0; i < CH; i++) {
        int idx = base + i;
        if (idx < N_NODES) {
            g_rowstart[idx] = run;
            g_cursor[idx] = run;
            run += g_hist[idx];
        }
    }
    if (t == 1023) g_rowstart[N_NODES] = psum[1023];
}

__global__ void fill_kernel(const int* __restrict__ src, const int* __restrict__ dst) {
    int e = blockIdx.x * blockDim.x + threadIdx.x;
    if (e < N_EDGES) {
        int pos = atomicAdd(&g_cursor[dst[e]], 1);
        g_col[pos] = src[e];
    }
}

// ---------------- aggregation: one warp per node, registers, pre-scaled ----------------
__global__ void aggregate_kernel(const float* __restrict__ h, float* __restrict__ hneigh) {
    int node = (blockIdx.x * blockDim.x + threadIdx.x) >> 5;
    int lane = threadIdx.x & 31;
    if (node >= N_NODES) return;
    int beg = g_rowstart[node];
    int end = g_rowstart[node + 1];
    float4 acc = make_float4(0.f, 0.f, 0.f, 0.f);
    int i = beg;
    for (; i + 4 <= end; i += 4) {
        int s0 = g_col[i + 0];
        int s1 = g_col[i + 1];
        int s2 = g_col[i + 2];
        int s3 = g_col[i + 3];
        float4 v0 = reinterpret_cast<const float4*>(h + (size_t)s0 * D)[lane];
        float4 v1 = reinterpret_cast<const float4*>(h + (size_t)s1 * D)[lane];
        float4 v2 = reinterpret_cast<const float4*>(h + (size_t)s2 * D)[lane];
        float4 v3 = reinterpret_cast<const float4*>(h + (size_t)s3 * D)[lane];
        acc.x += (v0.x + v1.x) + (v2.x + v3.x);
        acc.y += (v0.y + v1.y) + (v2.y + v3.y);
        acc.z += (v0.z + v1.z) + (v2.z + v3.z);
        acc.w += (v0.w + v1.w) + (v2.w + v3.w);
    }
    for (; i < end; ++i) {
        int s = g_col[i];
        float4 v = reinterpret_cast<const float4*>(h + (size_t)s * D)[lane];
        acc.x += v.x; acc.y += v.y; acc.z += v.z; acc.w += v.w;
    }
    float sc = 1.0f / fmaxf((float)(end - beg), 1.0f);
    reinterpret_cast<float4*>(hneigh + (size_t)node * D)[lane] =
        make_float4(acc.x * sc, acc.y * sc, acc.z * sc, acc.w * sc);
}

// ---------------- fused dual GEMM: out = h@Ws + hneigh@Wn + b (hneigh pre-scaled)
// 128x128 tile, BK=32, 256 threads, 8x8 register tile, k-major A in smem.
__global__ void __launch_bounds__(256, 2)
gemm_kernel(const float* __restrict__ h,
            const float* __restrict__ hn,
            const float* __restrict__ Ws,
            const float* __restrict__ Wn,
            const float* __restrict__ bias,
            float* __restrict__ out, int relu) {
    __shared__ float sA[GBK][GBM + 4];
    __shared__ float sW[GBK][D];

    const int tid = threadIdx.x;
    const int tx = tid & 15;   // column group (16)
    const int ty = tid >> 4;   // row group (16)
    const int m0 = blockIdx.x * GBM;

    float acc[8][8];
    #pragma unroll
    for (int i = 0; i < 8; i++)
        #pragma unroll
        for (int j = 0; j < 8; j++) acc[i][j] = 0.f;

    #pragma unroll 1
    for (int part = 0; part < 2; ++part) {
        const float* A = part ? hn : h;
        const float* W = part ? Wn : Ws;
        #pragma unroll 1
        for (int kc = 0; kc < D / GBK; ++kc) {
            __syncthreads();
            // stage A: 128 rows x 32 k, transposed to k-major
            #pragma unroll
            for (int it = 0; it < 4; ++it) {
                int li = tid + it * 256;   // 0..1023
                int row = li >> 3;
                int kg = li & 7;
                int gm = m0 + row;
                float4 v = (gm < N_NODES)
                    ? *reinterpret_cast<const float4*>(A + (size_t)gm * D + kc * GBK + kg * 4)
                    : make_float4(0.f, 0.f, 0.f, 0.f);
                sA[kg * 4 + 0][row] = v.x;
                sA[kg * 4 + 1][row] = v.y;
                sA[kg * 4 + 2][row] = v.z;
                sA[kg * 4 + 3][row] = v.w;
            }
            // stage W: 32 k x 128 cols (row-major, no transpose)
            #pragma unroll
            for (int it = 0; it < 4; ++it) {
                int li = tid + it * 256;
                int k = li >> 5;
                int g = li & 31;
                *reinterpret_cast<float4*>(&sW[k][g * 4]) =
                    *reinterpret_cast<const float4*>(W + (size_t)(kc * GBK + k) * D + g * 4);
            }
            __syncthreads();
            #pragma unroll
            for (int k = 0; k < GBK; ++k) {
                float4 a0 = *reinterpret_cast<const float4*>(&sA[k][ty * 4]);
                float4 a1 = *reinterpret_cast<const float4*>(&sA[k][64 + ty * 4]);
                float4 w0 = *reinterpret_cast<const float4*>(&sW[k][tx * 4]);
                float4 w1 = *reinterpret_cast<const float4*>(&sW[k][64 + tx * 4]);
                float av[8] = {a0.x, a0.y, a0.z, a0.w, a1.x, a1.y, a1.z, a1.w};
                float wv[8] = {w0.x, w0.y, w0.z, w0.w, w1.x, w1.y, w1.z, w1.w};
                #pragma unroll
                for (int i = 0; i < 8; i++)
                    #pragma unroll
                    for (int j = 0; j < 8; j++)
                        acc[i][j] += av[i] * wv[j];
            }
        }
    }

    // epilogue: bias + optional relu
    #pragma unroll
    for (int i = 0; i < 8; i++) {
        int gm = m0 + ((i < 4) ? (ty * 4 + i) : (64 + ty * 4 + (i - 4)));
        if (gm >= N_NODES) continue;
        float4 o0, o1;
        o0.x = acc[i][0] + bias[tx * 4 + 0];
        o0.y = acc[i][1] + bias[tx * 4 + 1];
        o0.z = acc[i][2] + bias[tx * 4 + 2];
        o0.w = acc[i][3] + bias[tx * 4 + 3];
        o1.x = acc[i][4] + bias[64 + tx * 4 + 0];
        o1.y = acc[i][5] + bias[64 + tx * 4 + 1];
        o1.z = acc[i][6] + bias[64 + tx * 4 + 2];
        o1.w = acc[i][7] + bias[64 + tx * 4 + 3];
        if (relu) {
            o0.x = fmaxf(o0.x, 0.f); o0.y = fmaxf(o0.y, 0.f);
            o0.z = fmaxf(o0.z, 0.f); o0.w = fmaxf(o0.w, 0.f);
            o1.x = fmaxf(o1.x, 0.f); o1.y = fmaxf(o1.y, 0.f);
            o1.z = fmaxf(o1.z, 0.f); o1.w = fmaxf(o1.w, 0.f);
        }
        reinterpret_cast<float4*>(out + (size_t)gm * D + tx * 4)[0] = o0;
        reinterpret_cast<float4*>(out + (size_t)gm * D + 64 + tx * 4)[0] = o1;
    }
}

// ---------------- launch ----------------
extern "C" void kernel_launch(void* const* d_in, const int* in_sizes, int n_in,
                              void* d_out, int out_size) {
    const float* features = (const float*)d_in[0];
    const int* src = (const int*)d_in[1];
    const int* dst = (const int*)d_in[2];
    const float* Ws[3] = {(const float*)d_in[3], (const float*)d_in[6], (const float*)d_in[9]};
    const float* Wn[3] = {(const float*)d_in[4], (const float*)d_in[7], (const float*)d_in[10]};
    const float* bb[3] = {(const float*)d_in[5], (const float*)d_in[8], (const float*)d_in[11]};
    float* out = (float*)d_out;

    void *p_hneigh, *p_h0, *p_h1, *p_hist;
    cudaGetSymbolAddress(&p_hneigh, g_hneigh);
    cudaGetSymbolAddress(&p_h0, g_hbuf0);
    cudaGetSymbolAddress(&p_h1, g_hbuf1);
    cudaGetSymbolAddress(&p_hist, g_hist);

    // CSR build (graph identical across layers)
    cudaMemsetAsync(p_hist, 0, N_NODES * sizeof(int));
    hist_kernel<<<(N_EDGES + 255) / 256, 256>>>(dst);
    scan_kernel<<<1, 1024>>>();
    fill_kernel<<<(N_EDGES + 255) / 256, 256>>>(src, dst);

    const float* hin = features;
    float* bufs[3] = {(float*)p_h0, (float*)p_h1, out};
    for (int l = 0; l < 3; ++l) {
        aggregate_kernel<<<(N_NODES * 32 + 255) / 256, 256>>>(hin, (float*)p_hneigh);
        gemm_kernel<<<(N_NODES + GBM - 1) / GBM, 256>>>(
            hin, (float*)p_hneigh, Ws[l], Wn[l], bb[l], bufs[l], (l < 2) ? 1 : 0);
        hin = bufs[l];
    }
}

// round 4
// speedup vs baseline: 2.8151x; 1.0731x over previous
#include <cuda_runtime.h>
#include <cuda_bf16.h>
#include <cstdint>

#define N_NODES 50000
#define N_EDGES 800000
#define D 128
#define KC 64   // k-chunk staged in smem

// ==================== scratch (no allocations allowed) ====================
__device__ float g_hneigh[(size_t)N_NODES * D];
__device__ float g_hbuf0[(size_t)N_NODES * D];
__device__ float g_hbuf1[(size_t)N_NODES * D];
__device__ int g_hist[N_NODES];
__device__ int g_cursor[N_NODES];
__device__ int g_rowstart[N_NODES + 1];
__device__ int g_col[N_EDGES];
// pre-swizzled bf16 W^T images: [matrix 0..5][hi=0/lo=1][2 kchunks x 128 rows x 64 cols]
__device__ __align__(128) __nv_bfloat16 g_Bimg[6][2][D * D];

// XOR swizzle: row-major 64 bf16 per row (128B), 8 chunks of 16B, chunk ^= row&7
__device__ __forceinline__ uint32_t swz(uint32_t row, uint32_t kbyte) {
    return row * 128u + ((((kbyte >> 4) ^ (row & 7u)) << 4) | (kbyte & 15u));
}

__device__ __forceinline__ uint32_t smem_u32(const void* p) {
    uint32_t a;
    asm("{ .reg .u64 t; cvta.to.shared.u64 t, %1; cvt.u32.u64 %0, t; }" : "=r"(a) : "l"(p));
    return a;
}

__device__ __forceinline__ void ldsm_x4(uint32_t addr, uint32_t& r0, uint32_t& r1,
                                        uint32_t& r2, uint32_t& r3) {
    asm volatile("ldmatrix.sync.aligned.m8n8.x4.shared.b16 {%0,%1,%2,%3}, [%4];"
                 : "=r"(r0), "=r"(r1), "=r"(r2), "=r"(r3) : "r"(addr));
}

__device__ __forceinline__ void mma_16816(float* c, const uint32_t* a, const uint32_t* b) {
    asm volatile(
        "mma.sync.aligned.m16n8k16.row.col.f32.bf16.bf16.f32 "
        "{%0,%1,%2,%3}, {%4,%5,%6,%7}, {%8,%9}, {%0,%1,%2,%3};"
        : "+f"(c[0]), "+f"(c[1]), "+f"(c[2]), "+f"(c[3])
        : "r"(a[0]), "r"(a[1]), "r"(a[2]), "r"(a[3]), "r"(b[0]), "r"(b[1]));
}

// ==================== CSR build ====================
__global__ void hist_kernel(const int* __restrict__ dst) {
    int e = blockIdx.x * blockDim.x + threadIdx.x;
    if (e < N_EDGES) atomicAdd(&g_hist[dst[e]], 1);
}

__global__ void scan_kernel() {
    __shared__ int psum[1024];
    const int CH = (N_NODES + 1023) / 1024;
    int t = threadIdx.x;
    int base = t * CH;
    int s = 0;
    for (int i = 0; i < CH; i++) {
        int idx = base + i;
        if (idx < N_NODES) s += g_hist[idx];
    }
    psum[t] = s;
    __syncthreads();
    for (int off = 1; off < 1024; off <<= 1) {
        int v = psum[t];
        int add = (t >= off) ? psum[t - off] : 0;
        __syncthreads();
        psum[t] = v + add;
        __syncthreads();
    }
    int run = (t == 0) ? 0 : psum[t - 1];
    for (int i = 0; i < CH; i++) {
        int idx = base + i;
        if (idx < N_NODES) {
            g_rowstart[idx] = run;
            g_cursor[idx] = run;
            run += g_hist[idx];
        }
    }
    if (t == 1023) g_rowstart[N_NODES] = psum[1023];
}

__global__ void fill_kernel(const int* __restrict__ src, const int* __restrict__ dst) {
    int e = blockIdx.x * blockDim.x + threadIdx.x;
    if (e < N_EDGES) {
        int pos = atomicAdd(&g_cursor[dst[e]], 1);
        g_col[pos] = src[e];
    }
}

// ==================== aggregation: warp/node, pre-scaled by 1/deg ====================
__global__ void aggregate_kernel(const float* __restrict__ h, float* __restrict__ hneigh) {
    int node = (blockIdx.x * blockDim.x + threadIdx.x) >> 5;
    int lane = threadIdx.x & 31;
    if (node >= N_NODES) return;
    int beg = g_rowstart[node];
    int end = g_rowstart[node + 1];
    float4 acc = make_float4(0.f, 0.f, 0.f, 0.f);
    int i = beg;
    for (; i + 4 <= end; i += 4) {
        int s0 = g_col[i + 0];
        int s1 = g_col[i + 1];
        int s2 = g_col[i + 2];
        int s3 = g_col[i + 3];
        float4 v0 = reinterpret_cast<const float4*>(h + (size_t)s0 * D)[lane];
        float4 v1 = reinterpret_cast<const float4*>(h + (size_t)s1 * D)[lane];
        float4 v2 = reinterpret_cast<const float4*>(h + (size_t)s2 * D)[lane];
        float4 v3 = reinterpret_cast<const float4*>(h + (size_t)s3 * D)[lane];
        acc.x += (v0.x + v1.x) + (v2.x + v3.x);
        acc.y += (v0.y + v1.y) + (v2.y + v3.y);
        acc.z += (v0.z + v1.z) + (v2.z + v3.z);
        acc.w += (v0.w + v1.w) + (v2.w + v3.w);
    }
    for (; i < end; ++i) {
        int s = g_col[i];
        float4 v = reinterpret_cast<const float4*>(h + (size_t)s * D)[lane];
        acc.x += v.x; acc.y += v.y; acc.z += v.z; acc.w += v.w;
    }
    float sc = 1.0f / fmaxf((float)(end - beg), 1.0f);
    reinterpret_cast<float4*>(hneigh + (size_t)node * D)[lane] =
        make_float4(acc.x * sc, acc.y * sc, acc.z * sc, acc.w * sc);
}

// ==================== weight prep: W[k][n] -> swizzled k-major W^T hi/lo images ====
__global__ void prep_weights(const float* W0s, const float* W0n, const float* W1s,
                             const float* W1n, const float* W2s, const float* W2n) {
    const float* Wp[6] = {W0s, W0n, W1s, W1n, W2s, W2n};
    const float* W = Wp[blockIdx.x];
    char* hi = (char*)g_Bimg[blockIdx.x][0];
    char* lo = (char*)g_Bimg[blockIdx.x][1];
    for (int idx = threadIdx.x; idx < 128 * 64; idx += blockDim.x) {
        int n = idx >> 6;             // output-feature row 0..127
        int kp = idx & 63;            // k pair index; k = kp*2
        int k = kp * 2;
        int kc = k >> 6;              // k chunk 0/1
        int kk = k & 63;              // k within chunk (even)
        float a0 = W[(size_t)k * D + n];
        float a1 = W[(size_t)(k + 1) * D + n];
        __nv_bfloat16 h0 = __float2bfloat16(a0);
        __nv_bfloat16 h1 = __float2bfloat16(a1);
        __nv_bfloat16 l0 = __float2bfloat16(a0 - __bfloat162float(h0));
        __nv_bfloat16 l1 = __float2bfloat16(a1 - __bfloat162float(h1));
        uint32_t hp = (uint32_t)__bfloat16_as_ushort(h0) | ((uint32_t)__bfloat16_as_ushort(h1) << 16);
        uint32_t lp = (uint32_t)__bfloat16_as_ushort(l0) | ((uint32_t)__bfloat16_as_ushort(l1) << 16);
        uint32_t off = (uint32_t)kc * 16384u + swz((uint32_t)n, (uint32_t)(kk * 2));
        *(uint32_t*)(hi + off) = hp;
        *(uint32_t*)(lo + off) = lp;
    }
}

// ==================== HMMA dual GEMM, bf16 3-term split ====================
// out[128x128 tile] = h@Ws + hneigh@Wn + bias, optional relu. fp32 accum.
__global__ void __launch_bounds__(256, 2)
gemm_hmma_kernel(const float* __restrict__ h, const float* __restrict__ hn,
                 const __nv_bfloat16* __restrict__ Bs, const __nv_bfloat16* __restrict__ Bn,
                 const float* __restrict__ bias, float* __restrict__ out, int relu) {
    extern __shared__ char dyn_smem[];
    uint32_t sbase = (smem_u32(dyn_smem) + 127u) & ~127u;
    char* smem0 = dyn_smem + (sbase - smem_u32(dyn_smem));
    const uint32_t sAh = sbase;
    const uint32_t sAl = sbase + 16384;
    const uint32_t sBh = sbase + 32768;
    const uint32_t sBl = sbase + 49152;

    const int tid = threadIdx.x;
    const int wid = tid >> 5;
    const int lane = tid & 31;
    const int m0 = blockIdx.x * 128;
    const int wm = (wid >> 2) * 64;   // warp m offset (0 / 64)
    const int wn = (wid & 3) * 32;    // warp n offset (0/32/64/96)

    float acc[4][4][4];
    #pragma unroll
    for (int i = 0; i < 4; i++)
        #pragma unroll
        for (int j = 0; j < 4; j++)
            #pragma unroll
            for (int r = 0; r < 4; r++) acc[i][j][r] = 0.f;

    #pragma unroll 1
    for (int part = 0; part < 2; ++part) {
        const float* A = part ? hn : h;
        const char* Bimg = (const char*)(part ? Bn : Bs);          // hi image
        const char* BimgLo = Bimg + 32768;                          // lo image
        #pragma unroll 1
        for (int kc = 0; kc < 2; ++kc) {
            __syncthreads();
            // ---- stage A: 128 rows x 64 k, fp32 -> bf16 hi/lo, swizzled ----
            #pragma unroll 4
            for (int it = 0; it < 16; ++it) {
                int idx = tid + it * 256;      // 0..4095
                int row = idx >> 5;
                int ki = (idx & 31) * 2;       // within-chunk k (even)
                int gm = m0 + row;
                float2 a = (gm < N_NODES)
                    ? *reinterpret_cast<const float2*>(A + (size_t)gm * D + kc * KC + ki)
                    : make_float2(0.f, 0.f);
                __nv_bfloat16 h0 = __float2bfloat16(a.x);
                __nv_bfloat16 h1 = __float2bfloat16(a.y);
                __nv_bfloat16 l0 = __float2bfloat16(a.x - __bfloat162float(h0));
                __nv_bfloat16 l1 = __float2bfloat16(a.y - __bfloat162float(h1));
                uint32_t hp = (uint32_t)__bfloat16_as_ushort(h0) | ((uint32_t)__bfloat16_as_ushort(h1) << 16);
                uint32_t lp = (uint32_t)__bfloat16_as_ushort(l0) | ((uint32_t)__bfloat16_as_ushort(l1) << 16);
                uint32_t off = swz((uint32_t)row, (uint32_t)(ki * 2));
                *(uint32_t*)(smem0 + off) = hp;              // sAh
                *(uint32_t*)(smem0 + 16384 + off) = lp;      // sAl
            }
            // ---- stage B: raw copy of pre-swizzled 16KB hi + 16KB lo ----
            {
                const float4* srch = reinterpret_cast<const float4*>(Bimg + kc * 16384);
                const float4* srcl = reinterpret_cast<const float4*>(BimgLo + kc * 16384);
                float4* dsth = reinterpret_cast<float4*>(smem0 + 32768);
                float4* dstl = reinterpret_cast<float4*>(smem0 + 49152);
                #pragma unroll
                for (int i = 0; i < 4; ++i) {
                    dsth[tid + i * 256] = srch[tid + i * 256];
                    dstl[tid + i * 256] = srcl[tid + i * 256];
                }
            }
            __syncthreads();

            // ---- compute: 3 chains x 4 k16-steps x (4 A-ldsm + 2 B-ldsm + 16 mma) ----
            const uint32_t aSel[3] = {sAh, sAh, sAl};
            const uint32_t bSel[3] = {sBh, sBl, sBh};
            #pragma unroll
            for (int c = 0; c < 3; ++c) {
                const uint32_t ab = aSel[c];
                const uint32_t bb = bSel[c];
                #pragma unroll
                for (int ks = 0; ks < 4; ++ks) {
                    uint32_t a[4][4];
                    #pragma unroll
                    for (int i = 0; i < 4; ++i) {
                        uint32_t row = wm + i * 16 + (lane & 15);
                        uint32_t kbyte = ks * 32 + ((lane >> 4) << 4);
                        ldsm_x4(ab + swz(row, kbyte), a[i][0], a[i][1], a[i][2], a[i][3]);
                    }
                    uint32_t b[4][2];
                    #pragma unroll
                    for (int jj = 0; jj < 2; ++jj) {
                        uint32_t mi = (uint32_t)lane >> 3;
                        uint32_t row = wn + jj * 16 + ((mi >> 1) << 3) + (lane & 7);
                        uint32_t kbyte = ks * 32 + ((mi & 1) << 4);
                        uint32_t r0, r1, r2, r3;
                        ldsm_x4(bb + swz(row, kbyte), r0, r1, r2, r3);
                        b[jj * 2 + 0][0] = r0; b[jj * 2 + 0][1] = r1;
                        b[jj * 2 + 1][0] = r2; b[jj * 2 + 1][1] = r3;
                    }
                    #pragma unroll
                    for (int i = 0; i < 4; ++i)
                        #pragma unroll
                        for (int j = 0; j < 4; ++j)
                            mma_16816(acc[i][j], a[i], b[j]);
                }
            }
        }
    }

    // ---- epilogue: bias + optional relu, float2 stores ----
    #pragma unroll
    for (int i = 0; i < 4; ++i) {
        int r0 = m0 + wm + i * 16 + (lane >> 2);
        #pragma unroll
        for (int j = 0; j < 4; ++j) {
            int col = wn + j * 8 + (lane & 3) * 2;
            float bx = bias[col], by = bias[col + 1];
            float2 lo = make_float2(acc[i][j][0] + bx, acc[i][j][1] + by);
            float2 hi2 = make_float2(acc[i][j][2] + bx, acc[i][j][3] + by);
            if (relu) {
                lo.x = fmaxf(lo.x, 0.f); lo.y = fmaxf(lo.y, 0.f);
                hi2.x = fmaxf(hi2.x, 0.f); hi2.y = fmaxf(hi2.y, 0.f);
            }
            if (r0 < N_NODES)
                *reinterpret_cast<float2*>(out + (size_t)r0 * D + col) = lo;
            if (r0 + 8 < N_NODES)
                *reinterpret_cast<float2*>(out + (size_t)(r0 + 8) * D + col) = hi2;
        }
    }
}

// ==================== launch ====================
extern "C" void kernel_launch(void* const* d_in, const int* in_sizes, int n_in,
                              void* d_out, int out_size) {
    const float* features = (const float*)d_in[0];
    const int* src = (const int*)d_in[1];
    const int* dst = (const int*)d_in[2];
    const float* Ws[3] = {(const float*)d_in[3], (const float*)d_in[6], (const float*)d_in[9]};
    const float* Wn[3] = {(const float*)d_in[4], (const float*)d_in[7], (const float*)d_in[10]};
    const float* bb[3] = {(const float*)d_in[5], (const float*)d_in[8], (const float*)d_in[11]};
    float* out = (float*)d_out;

    void *p_hneigh, *p_h0, *p_h1, *p_hist, *p_bimg;
    cudaGetSymbolAddress(&p_hneigh, g_hneigh);
    cudaGetSymbolAddress(&p_h0, g_hbuf0);
    cudaGetSymbolAddress(&p_h1, g_hbuf1);
    cudaGetSymbolAddress(&p_hist, g_hist);
    cudaGetSymbolAddress(&p_bimg, g_Bimg);
    __nv_bfloat16* bimg = (__nv_bfloat16*)p_bimg;
    auto img = [&](int mat) { return bimg + (size_t)mat * 2 * D * D; };  // hi; lo at +D*D

    const size_t smem_bytes = 65536 + 128;
    cudaFuncSetAttribute(gemm_hmma_kernel, cudaFuncAttributeMaxDynamicSharedMemorySize,
                         (int)smem_bytes);

    // CSR build + weight prep (graph identical across layers)
    cudaMemsetAsync(p_hist, 0, N_NODES * sizeof(int));
    hist_kernel<<<(N_EDGES + 255) / 256, 256>>>(dst);
    prep_weights<<<6, 256>>>(Ws[0], Wn[0], Ws[1], Wn[1], Ws[2], Wn[2]);
    scan_kernel<<<1, 1024>>>();
    fill_kernel<<<(N_EDGES + 255) / 256, 256>>>(src, dst);

    const float* hin = features;
    float* bufs[3] = {(float*)p_h0, (float*)p_h1, out};
    const int ntiles = (N_NODES + 127) / 128;
    for (int l = 0; l < 3; ++l) {
        aggregate_kernel<<<(N_NODES * 32 + 255) / 256, 256>>>(hin, (float*)p_hneigh);
        gemm_hmma_kernel<<<ntiles, 256, smem_bytes>>>(
            hin, (float*)p_hneigh, img(l * 2 + 0), img(l * 2 + 1),
            bb[l], bufs[l], (l < 2) ? 1 : 0);
        hin = bufs[l];
    }
}

// round 5
// speedup vs baseline: 3.0973x; 1.1003x over previous
#include <cuda_runtime.h>
#include <cuda_bf16.h>
#include <cstdint>

#define N_NODES 50000
#define N_EDGES 800000
#define D 128
#define NT 391            // ceil(N_NODES/128)

// ==================== scratch (no allocations allowed) ====================
__device__ float g_hbuf0[(size_t)N_NODES * D];
__device__ float g_hbuf1[(size_t)N_NODES * D];
__device__ int g_hist[N_NODES];
__device__ int g_cursor[N_NODES];
__device__ int g_rowstart[N_NODES + 1];
__device__ int g_col[N_EDGES];
// pre-swizzled bf16 W^T images: [matrix 0..5][hi=0/lo=1][2 kchunks x 128 x 64]
__device__ __align__(128) __nv_bfloat16 g_Bimg[6][2][D * D];
// node-feature tile images: [set][hi/lo][tile*16384 bf16] (32KB per tile: kc0|kc1)
__device__ __align__(128) __nv_bfloat16 g_imgA[2][2][(size_t)NT * 16384];
// hneigh tile images: [hi/lo]
__device__ __align__(128) __nv_bfloat16 g_imgN[2][(size_t)NT * 16384];

// XOR swizzle: row-major 64 bf16 per row (128B), 8 chunks of 16B, chunk ^= row&7
__device__ __forceinline__ uint32_t swz(uint32_t row, uint32_t kbyte) {
    return row * 128u + ((((kbyte >> 4) ^ (row & 7u)) << 4) | (kbyte & 15u));
}

__device__ __forceinline__ uint32_t smem_u32(const void* p) {
    uint32_t a;
    asm("{ .reg .u64 t; cvta.to.shared.u64 t, %1; cvt.u32.u64 %0, t; }" : "=r"(a) : "l"(p));
    return a;
}
__device__ __forceinline__ void cp_async16(uint32_t saddr, const void* gptr) {
    asm volatile("cp.async.cg.shared.global [%0], [%1], 16;" :: "r"(saddr), "l"(gptr));
}
#define CP_COMMIT() asm volatile("cp.async.commit_group;" ::: "memory")
#define CP_WAIT0()  asm volatile("cp.async.wait_group 0;" ::: "memory")

__device__ __forceinline__ void ldsm_x4(uint32_t addr, uint32_t& r0, uint32_t& r1,
                                        uint32_t& r2, uint32_t& r3) {
    asm volatile("ldmatrix.sync.aligned.m8n8.x4.shared.b16 {%0,%1,%2,%3}, [%4];"
                 : "=r"(r0), "=r"(r1), "=r"(r2), "=r"(r3) : "r"(addr));
}
__device__ __forceinline__ void mma_16816(float* c, const uint32_t* a, const uint32_t* b) {
    asm volatile(
        "mma.sync.aligned.m16n8k16.row.col.f32.bf16.bf16.f32 "
        "{%0,%1,%2,%3}, {%4,%5,%6,%7}, {%8,%9}, {%0,%1,%2,%3};"
        : "+f"(c[0]), "+f"(c[1]), "+f"(c[2]), "+f"(c[3])
        : "r"(a[0]), "r"(a[1]), "r"(a[2]), "r"(a[3]), "r"(b[0]), "r"(b[1]));
}
// split x,y into packed bf16x2 hi + bf16x2 lo(residual)
__device__ __forceinline__ void split2(float x, float y, uint32_t& hp, uint32_t& lp) {
    __nv_bfloat16 hx = __float2bfloat16(x);
    __nv_bfloat16 hy = __float2bfloat16(y);
    __nv_bfloat16 lx = __float2bfloat16(x - __bfloat162float(hx));
    __nv_bfloat16 ly = __float2bfloat16(y - __bfloat162float(hy));
    hp = (uint32_t)__bfloat16_as_ushort(hx) | ((uint32_t)__bfloat16_as_ushort(hy) << 16);
    lp = (uint32_t)__bfloat16_as_ushort(lx) | ((uint32_t)__bfloat16_as_ushort(ly) << 16);
}

// ==================== CSR build ====================
__global__ void hist_kernel(const int* __restrict__ dst) {
    int e = blockIdx.x * blockDim.x + threadIdx.x;
    if (e < N_EDGES) atomicAdd(&g_hist[dst[e]], 1);
}

__global__ void scan_kernel() {
    __shared__ int psum[1024];
    const int CH = (N_NODES + 1023) / 1024;
    int t = threadIdx.x;
    int base = t * CH;
    int s = 0;
    for (int i = 0; i < CH; i++) {
        int idx = base + i;
        if (idx < N_NODES) s += g_hist[idx];
    }
    psum[t] = s;
    __syncthreads();
    for (int off = 1; off < 1024; off <<= 1) {
        int v = psum[t];
        int add = (t >= off) ? psum[t - off] : 0;
        __syncthreads();
        psum[t] = v + add;
        __syncthreads();
    }
    int run = (t == 0) ? 0 : psum[t - 1];
    for (int i = 0; i < CH; i++) {
        int idx = base + i;
        if (idx < N_NODES) {
            g_rowstart[idx] = run;
            g_cursor[idx] = run;
            run += g_hist[idx];
        }
    }
    if (t == 1023) g_rowstart[N_NODES] = psum[1023];
}

__global__ void fill_kernel(const int* __restrict__ src, const int* __restrict__ dst) {
    int e = blockIdx.x * blockDim.x + threadIdx.x;
    if (e < N_EDGES) {
        int pos = atomicAdd(&g_cursor[dst[e]], 1);
        g_col[pos] = src[e];
    }
}

// ==================== features fp32 -> tile images (set 0) ====================
__global__ void convert_features(const float* __restrict__ h, char* __restrict__ hi,
                                 char* __restrict__ lo) {
    int tile = blockIdx.x;
    int m0 = tile * 128;
    #pragma unroll 4
    for (int it = 0; it < 32; ++it) {
        int idx = threadIdx.x + it * 256;   // 0..8191
        int row = idx >> 6;
        int k = (idx & 63) * 2;
        int gm = m0 + row;
        float2 a = (gm < N_NODES) ? *reinterpret_cast<const float2*>(h + (size_t)gm * D + k)
                                  : make_float2(0.f, 0.f);
        uint32_t hp, lp;
        split2(a.x, a.y, hp, lp);
        uint32_t off = (uint32_t)tile * 32768u + (uint32_t)(k >> 6) * 16384u
                     + swz((uint32_t)row, (uint32_t)((k & 63) * 2));
        *(uint32_t*)(hi + off) = hp;
        *(uint32_t*)(lo + off) = lp;
    }
}

// ==================== aggregation: warp/node -> hneigh images directly ============
__global__ void aggregate_kernel(const float* __restrict__ h, char* __restrict__ nhi,
                                 char* __restrict__ nlo) {
    int node = (blockIdx.x * blockDim.x + threadIdx.x) >> 5;
    int lane = threadIdx.x & 31;
    if (node >= N_NODES) return;
    int beg = g_rowstart[node];
    int end = g_rowstart[node + 1];
    float4 acc = make_float4(0.f, 0.f, 0.f, 0.f);
    int i = beg;
    for (; i + 4 <= end; i += 4) {
        int s0 = g_col[i + 0];
        int s1 = g_col[i + 1];
        int s2 = g_col[i + 2];
        int s3 = g_col[i + 3];
        float4 v0 = reinterpret_cast<const float4*>(h + (size_t)s0 * D)[lane];
        float4 v1 = reinterpret_cast<const float4*>(h + (size_t)s1 * D)[lane];
        float4 v2 = reinterpret_cast<const float4*>(h + (size_t)s2 * D)[lane];
        float4 v3 = reinterpret_cast<const float4*>(h + (size_t)s3 * D)[lane];
        acc.x += (v0.x + v1.x) + (v2.x + v3.x);
        acc.y += (v0.y + v1.y) + (v2.y + v3.y);
        acc.z += (v0.z + v1.z) + (v2.z + v3.z);
        acc.w += (v0.w + v1.w) + (v2.w + v3.w);
    }
    for (; i < end; ++i) {
        int s = g_col[i];
        float4 v = reinterpret_cast<const float4*>(h + (size_t)s * D)[lane];
        acc.x += v.x; acc.y += v.y; acc.z += v.z; acc.w += v.w;
    }
    float sc = 1.0f / fmaxf((float)(end - beg), 1.0f);
    acc.x *= sc; acc.y *= sc; acc.z *= sc; acc.w *= sc;
    // write swizzled bf16 hi/lo image: lane covers k = lane*4 .. lane*4+3
    int tile = node >> 7;
    int row = node & 127;
    int k0 = lane * 4;
    uint32_t off = (uint32_t)tile * 32768u + (uint32_t)(k0 >> 6) * 16384u
                 + swz((uint32_t)row, (uint32_t)((k0 & 63) * 2));
    uint32_t h0, l0, h1, l1;
    split2(acc.x, acc.y, h0, l0);
    split2(acc.z, acc.w, h1, l1);
    *(uint2*)(nhi + off) = make_uint2(h0, h1);
    *(uint2*)(nlo + off) = make_uint2(l0, l1);
}

// ==================== weight prep: W[k][n] -> swizzled k-major W^T hi/lo images ====
__global__ void prep_weights(const float* W0s, const float* W0n, const float* W1s,
                             const float* W1n, const float* W2s, const float* W2n) {
    const float* Wp[6] = {W0s, W0n, W1s, W1n, W2s, W2n};
    int mat = blockIdx.x >> 3;
    int sub = blockIdx.x & 7;
    const float* W = Wp[mat];
    char* hi = (char*)g_Bimg[mat][0];
    char* lo = (char*)g_Bimg[mat][1];
    for (int t = threadIdx.x; t < 1024; t += blockDim.x) {
        int idx = sub * 1024 + t;          // 0..8191
        int n = idx >> 6;
        int k = (idx & 63) * 2;
        float a0 = W[(size_t)k * D + n];
        float a1 = W[(size_t)(k + 1) * D + n];
        uint32_t hp, lp;
        split2(a0, a1, hp, lp);
        uint32_t off = (uint32_t)(k >> 6) * 16384u + swz((uint32_t)n, (uint32_t)((k & 63) * 2));
        *(uint32_t*)(hi + off) = hp;
        *(uint32_t*)(lo + off) = lp;
    }
}

// ==================== HMMA dual GEMM from pre-swizzled images ====================
__global__ void __launch_bounds__(256, 2)
gemm_hmma_kernel(const char* __restrict__ imgAh, const char* __restrict__ imgAl,
                 const char* __restrict__ imgNh, const char* __restrict__ imgNl,
                 const char* __restrict__ Bs, const char* __restrict__ Bn,  // hi; lo at +32768
                 const float* __restrict__ bias, float* __restrict__ out,
                 char* __restrict__ oImgH, char* __restrict__ oImgL,
                 int relu, int write_img) {
    extern __shared__ char dyn_smem[];
    uint32_t sbase = (smem_u32(dyn_smem) + 127u) & ~127u;
    const uint32_t sAh = sbase;
    const uint32_t sAl = sbase + 16384;
    const uint32_t sBh = sbase + 32768;
    const uint32_t sBl = sbase + 49152;

    const int tid = threadIdx.x;
    const int wid = tid >> 5;
    const int lane = tid & 31;
    const int tile = blockIdx.x;
    const int m0 = tile * 128;
    const int wm = (wid >> 2) * 64;
    const int wn = (wid & 3) * 32;

    float acc[4][4][4];
    #pragma unroll
    for (int i = 0; i < 4; i++)
        #pragma unroll
        for (int j = 0; j < 4; j++)
            #pragma unroll
            for (int r = 0; r < 4; r++) acc[i][j][r] = 0.f;

    #pragma unroll 1
    for (int part = 0; part < 2; ++part) {
        const char* Ah = (part ? imgNh : imgAh) + (size_t)tile * 32768;
        const char* Al = (part ? imgNl : imgAl) + (size_t)tile * 32768;
        const char* Bh = part ? Bn : Bs;
        #pragma unroll 1
        for (int kc = 0; kc < 2; ++kc) {
            __syncthreads();   // previous compute done before overwrite
            const char* srcAh = Ah + kc * 16384;
            const char* srcAl = Al + kc * 16384;
            const char* srcBh = Bh + kc * 16384;
            const char* srcBl = Bh + 32768 + kc * 16384;
            #pragma unroll
            for (int i = 0; i < 4; ++i) {
                uint32_t o = (uint32_t)(tid + i * 256) * 16u;
                cp_async16(sAh + o, srcAh + o);
                cp_async16(sAl + o, srcAl + o);
                cp_async16(sBh + o, srcBh + o);
                cp_async16(sBl + o, srcBl + o);
            }
            CP_COMMIT();
            CP_WAIT0();
            __syncthreads();

            const uint32_t aSel[3] = {sAh, sAh, sAl};
            const uint32_t bSel[3] = {sBh, sBl, sBh};
            #pragma unroll
            for (int c = 0; c < 3; ++c) {
                const uint32_t ab = aSel[c];
                const uint32_t bb = bSel[c];
                #pragma unroll
                for (int ks = 0; ks < 4; ++ks) {
                    uint32_t a[4][4];
                    #pragma unroll
                    for (int i = 0; i < 4; ++i) {
                        uint32_t row = wm + i * 16 + (lane & 15);
                        uint32_t kbyte = ks * 32 + ((lane >> 4) << 4);
                        ldsm_x4(ab + swz(row, kbyte), a[i][0], a[i][1], a[i][2], a[i][3]);
                    }
                    uint32_t b[4][2];
                    #pragma unroll
                    for (int jj = 0; jj < 2; ++jj) {
                        uint32_t mi = (uint32_t)lane >> 3;
                        uint32_t row = wn + jj * 16 + ((mi >> 1) << 3) + (lane & 7);
                        uint32_t kbyte = ks * 32 + ((mi & 1) << 4);
                        uint32_t r0, r1, r2, r3;
                        ldsm_x4(bb + swz(row, kbyte), r0, r1, r2, r3);
                        b[jj * 2 + 0][0] = r0; b[jj * 2 + 0][1] = r1;
                        b[jj * 2 + 1][0] = r2; b[jj * 2 + 1][1] = r3;
                    }
                    #pragma unroll
                    for (int i = 0; i < 4; ++i)
                        #pragma unroll
                        for (int j = 0; j < 4; ++j)
                            mma_16816(acc[i][j], a[i], b[j]);
                }
            }
        }
    }

    // ---- epilogue: bias + relu; fp32 out + optional next-layer images ----
    #pragma unroll
    for (int i = 0; i < 4; ++i) {
        int rloc0 = wm + i * 16 + (lane >> 2);
        int r0 = m0 + rloc0;
        #pragma unroll
        for (int j = 0; j < 4; ++j) {
            int col = wn + j * 8 + (lane & 3) * 2;
            float bx = bias[col], by = bias[col + 1];
            float2 v0 = make_float2(acc[i][j][0] + bx, acc[i][j][1] + by);
            float2 v1 = make_float2(acc[i][j][2] + bx, acc[i][j][3] + by);
            if (relu) {
                v0.x = fmaxf(v0.x, 0.f); v0.y = fmaxf(v0.y, 0.f);
                v1.x = fmaxf(v1.x, 0.f); v1.y = fmaxf(v1.y, 0.f);
            }
            if (r0 < N_NODES)
                *reinterpret_cast<float2*>(out + (size_t)r0 * D + col) = v0;
            if (r0 + 8 < N_NODES)
                *reinterpret_cast<float2*>(out + (size_t)(r0 + 8) * D + col) = v1;
            if (write_img) {
                uint32_t obase = (uint32_t)tile * 32768u + (uint32_t)(col >> 6) * 16384u;
                uint32_t kb = (uint32_t)((col & 63) * 2);
                uint32_t hp, lp;
                if (r0 < N_NODES) {
                    split2(v0.x, v0.y, hp, lp);
                    uint32_t off = obase + swz((uint32_t)rloc0, kb);
                    *(uint32_t*)(oImgH + off) = hp;
                    *(uint32_t*)(oImgL + off) = lp;
                }
                if (r0 + 8 < N_NODES) {
                    split2(v1.x, v1.y, hp, lp);
                    uint32_t off = obase + swz((uint32_t)(rloc0 + 8), kb);
                    *(uint32_t*)(oImgH + off) = hp;
                    *(uint32_t*)(oImgL + off) = lp;
                }
            }
        }
    }
}

// ==================== launch ====================
extern "C" void kernel_launch(void* const* d_in, const int* in_sizes, int n_in,
                              void* d_out, int out_size) {
    const float* features = (const float*)d_in[0];
    const int* src = (const int*)d_in[1];
    const int* dst = (const int*)d_in[2];
    const float* Ws[3] = {(const float*)d_in[3], (const float*)d_in[6], (const float*)d_in[9]};
    const float* Wn[3] = {(const float*)d_in[4], (const float*)d_in[7], (const float*)d_in[10]};
    const float* bb[3] = {(const float*)d_in[5], (const float*)d_in[8], (const float*)d_in[11]};
    float* out = (float*)d_out;

    void *p_h0, *p_h1, *p_hist, *p_bimg, *p_imgA, *p_imgN;
    cudaGetSymbolAddress(&p_h0, g_hbuf0);
    cudaGetSymbolAddress(&p_h1, g_hbuf1);
    cudaGetSymbolAddress(&p_hist, g_hist);
    cudaGetSymbolAddress(&p_bimg, g_Bimg);
    cudaGetSymbolAddress(&p_imgA, g_imgA);
    cudaGetSymbolAddress(&p_imgN, g_imgN);

    char* bimg = (char*)p_bimg;
    auto wimg = [&](int mat) { return bimg + (size_t)mat * 65536; };  // hi; lo at +32768
    const size_t ISZ = (size_t)NT * 32768;  // bytes per image
    char* aimg = (char*)p_imgA;
    auto aimgp = [&](int set, int part) { return aimg + ((size_t)set * 2 + part) * ISZ; };
    char* nimg = (char*)p_imgN;

    const size_t smem_bytes = 65536 + 128;
    cudaFuncSetAttribute(gemm_hmma_kernel, cudaFuncAttributeMaxDynamicSharedMemorySize,
                         (int)smem_bytes);

    // prep: CSR + feature images + weight images
    cudaMemsetAsync(p_hist, 0, N_NODES * sizeof(int));
    hist_kernel<<<(N_EDGES + 255) / 256, 256>>>(dst);
    convert_features<<<NT, 256>>>(features, aimgp(0, 0), aimgp(0, 1));
    prep_weights<<<48, 256>>>(Ws[0], Wn[0], Ws[1], Wn[1], Ws[2], Wn[2]);
    scan_kernel<<<1, 1024>>>();
    fill_kernel<<<(N_EDGES + 255) / 256, 256>>>(src, dst);

    const float* hin = features;
    float* bufs[3] = {(float*)p_h0, (float*)p_h1, out};
    for (int l = 0; l < 3; ++l) {
        int rset = l & 1;            // 0,1,0
        int wset = 1 - rset;
        int wimg_flag = (l < 2) ? 1 : 0;
        aggregate_kernel<<<(N_NODES * 32 + 255) / 256, 256>>>(hin, nimg, nimg + ISZ);
        gemm_hmma_kernel<<<NT, 256, smem_bytes>>>(
            aimgp(rset, 0), aimgp(rset, 1), nimg, nimg + ISZ,
            wimg(l * 2 + 0), wimg(l * 2 + 1), bb[l], bufs[l],
            aimgp(wset, 0), aimgp(wset, 1), (l < 2) ? 1 : 0, wimg_flag);
        hin = bufs[l];
    }
}

// round 6
// speedup vs baseline: 3.8555x; 1.2448x over previous
#include <cuda_runtime.h>
#include <cuda_bf16.h>
#include <cstdint>

#define N_NODES 50000
#define N_EDGES 800000
#define D 128
#define NT 391            // ceil(N_NODES/128)
#define SCAN_BLOCKS 196   // 196*256 = 50176 >= N_NODES

// ==================== scratch (no allocations allowed) ====================
__device__ float g_hbuf0[(size_t)N_NODES * D];
__device__ float g_hbuf1[(size_t)N_NODES * D];
__device__ int g_hist[N_NODES];
__device__ int g_cursor[N_NODES];
__device__ int g_rowstart[N_NODES + 1];
__device__ int g_col[N_EDGES];
__device__ int g_blocksum[SCAN_BLOCKS];
__device__ int g_blockoff[SCAN_BLOCKS];
// pre-swizzled bf16 W^T images: [matrix 0..5][hi=0/lo=1][2 kchunks x 128 x 64]
__device__ __align__(128) __nv_bfloat16 g_Bimg[6][2][D * D];
// node-feature tile images: [set][hi/lo][tile*16384 bf16] (32KB per tile: kc0|kc1)
__device__ __align__(128) __nv_bfloat16 g_imgA[2][2][(size_t)NT * 16384];
// hneigh tile images: [hi/lo]
__device__ __align__(128) __nv_bfloat16 g_imgN[2][(size_t)NT * 16384];

// XOR swizzle: row-major 64 bf16 per row (128B), 8 chunks of 16B, chunk ^= row&7
__device__ __forceinline__ uint32_t swz(uint32_t row, uint32_t kbyte) {
    return row * 128u + ((((kbyte >> 4) ^ (row & 7u)) << 4) | (kbyte & 15u));
}

__device__ __forceinline__ uint32_t smem_u32(const void* p) {
    uint32_t a;
    asm("{ .reg .u64 t; cvta.to.shared.u64 t, %1; cvt.u32.u64 %0, t; }" : "=r"(a) : "l"(p));
    return a;
}
__device__ __forceinline__ void cp_async16(uint32_t saddr, const void* gptr) {
    asm volatile("cp.async.cg.shared.global [%0], [%1], 16;" :: "r"(saddr), "l"(gptr));
}
#define CP_COMMIT() asm volatile("cp.async.commit_group;" ::: "memory")
#define CP_WAIT0()  asm volatile("cp.async.wait_group 0;" ::: "memory")

__device__ __forceinline__ void ldsm_x4(uint32_t addr, uint32_t& r0, uint32_t& r1,
                                        uint32_t& r2, uint32_t& r3) {
    asm volatile("ldmatrix.sync.aligned.m8n8.x4.shared.b16 {%0,%1,%2,%3}, [%4];"
                 : "=r"(r0), "=r"(r1), "=r"(r2), "=r"(r3) : "r"(addr));
}
__device__ __forceinline__ void mma_16816(float* c, const uint32_t* a, const uint32_t* b) {
    asm volatile(
        "mma.sync.aligned.m16n8k16.row.col.f32.bf16.bf16.f32 "
        "{%0,%1,%2,%3}, {%4,%5,%6,%7}, {%8,%9}, {%0,%1,%2,%3};"
        : "+f"(c[0]), "+f"(c[1]), "+f"(c[2]), "+f"(c[3])
        : "r"(a[0]), "r"(a[1]), "r"(a[2]), "r"(a[3]), "r"(b[0]), "r"(b[1]));
}
// split x,y into packed bf16x2 hi + bf16x2 lo(residual)
__device__ __forceinline__ void split2(float x, float y, uint32_t& hp, uint32_t& lp) {
    __nv_bfloat16 hx = __float2bfloat16(x);
    __nv_bfloat16 hy = __float2bfloat16(y);
    __nv_bfloat16 lx = __float2bfloat16(x - __bfloat162float(hx));
    __nv_bfloat16 ly = __float2bfloat16(y - __bfloat162float(hy));
    hp = (uint32_t)__bfloat16_as_ushort(hx) | ((uint32_t)__bfloat16_as_ushort(hy) << 16);
    lp = (uint32_t)__bfloat16_as_ushort(lx) | ((uint32_t)__bfloat16_as_ushort(ly) << 16);
}

// ==================== CSR build ====================
__global__ void hist_kernel(const int* __restrict__ dst) {
    int e = blockIdx.x * blockDim.x + threadIdx.x;
    if (e < N_EDGES) atomicAdd(&g_hist[dst[e]], 1);
}

// phase 1: per-block inclusive scan of 256 degrees -> local exclusive + block sums
__global__ void scan_local() {
    __shared__ int sh[256];
    int t = threadIdx.x;
    int idx = blockIdx.x * 256 + t;
    int v = (idx < N_NODES) ? g_hist[idx] : 0;
    sh[t] = v;
    __syncthreads();
    #pragma unroll
    for (int off = 1; off < 256; off <<= 1) {
        int x = sh[t];
        int add = (t >= off) ? sh[t - off] : 0;
        __syncthreads();
        sh[t] = x + add;
        __syncthreads();
    }
    if (idx < N_NODES) g_rowstart[idx] = sh[t] - v;   // local exclusive
    if (t == 255) g_blocksum[blockIdx.x] = sh[255];
}

// phase 2: scan the 196 block sums (single tiny block)
__global__ void scan_blocks() {
    __shared__ int sh[256];
    int t = threadIdx.x;
    int v = (t < SCAN_BLOCKS) ? g_blocksum[t] : 0;
    sh[t] = v;
    __syncthreads();
    #pragma unroll
    for (int off = 1; off < 256; off <<= 1) {
        int x = sh[t];
        int add = (t >= off) ? sh[t - off] : 0;
        __syncthreads();
        sh[t] = x + add;
        __syncthreads();
    }
    if (t < SCAN_BLOCKS) g_blockoff[t] = sh[t] - v;   // exclusive
    if (t == 255) g_rowstart[N_NODES] = sh[255];       // total = N_EDGES
}

// phase 3: add block offsets, init cursors
__global__ void scan_apply() {
    int idx = blockIdx.x * 256 + threadIdx.x;
    if (idx < N_NODES) {
        int r = g_rowstart[idx] + g_blockoff[blockIdx.x];
        g_rowstart[idx] = r;
        g_cursor[idx] = r;
    }
}

__global__ void fill_kernel(const int* __restrict__ src, const int* __restrict__ dst) {
    int e = blockIdx.x * blockDim.x + threadIdx.x;
    if (e < N_EDGES) {
        int pos = atomicAdd(&g_cursor[dst[e]], 1);
        g_col[pos] = src[e];
    }
}

// ==================== features fp32 -> tile images (set 0) ====================
__global__ void convert_features(const float* __restrict__ h, char* __restrict__ hi,
                                 char* __restrict__ lo) {
    int tile = blockIdx.x;
    int m0 = tile * 128;
    #pragma unroll 4
    for (int it = 0; it < 32; ++it) {
        int idx = threadIdx.x + it * 256;   // 0..8191
        int row = idx >> 6;
        int k = (idx & 63) * 2;
        int gm = m0 + row;
        float2 a = (gm < N_NODES) ? *reinterpret_cast<const float2*>(h + (size_t)gm * D + k)
                                  : make_float2(0.f, 0.f);
        uint32_t hp, lp;
        split2(a.x, a.y, hp, lp);
        uint32_t off = (uint32_t)tile * 32768u + (uint32_t)(k >> 6) * 16384u
                     + swz((uint32_t)row, (uint32_t)((k & 63) * 2));
        *(uint32_t*)(hi + off) = hp;
        *(uint32_t*)(lo + off) = lp;
    }
}

// ==================== aggregation: warp/node -> hneigh images directly ============
__global__ void aggregate_kernel(const float* __restrict__ h, char* __restrict__ nhi,
                                 char* __restrict__ nlo) {
    int node = (blockIdx.x * blockDim.x + threadIdx.x) >> 5;
    int lane = threadIdx.x & 31;
    if (node >= N_NODES) return;
    int beg = g_rowstart[node];
    int end = g_rowstart[node + 1];
    float4 acc = make_float4(0.f, 0.f, 0.f, 0.f);
    int i = beg;
    for (; i + 4 <= end; i += 4) {
        int s0 = g_col[i + 0];
        int s1 = g_col[i + 1];
        int s2 = g_col[i + 2];
        int s3 = g_col[i + 3];
        float4 v0 = reinterpret_cast<const float4*>(h + (size_t)s0 * D)[lane];
        float4 v1 = reinterpret_cast<const float4*>(h + (size_t)s1 * D)[lane];
        float4 v2 = reinterpret_cast<const float4*>(h + (size_t)s2 * D)[lane];
        float4 v3 = reinterpret_cast<const float4*>(h + (size_t)s3 * D)[lane];
        acc.x += (v0.x + v1.x) + (v2.x + v3.x);
        acc.y += (v0.y + v1.y) + (v2.y + v3.y);
        acc.z += (v0.z + v1.z) + (v2.z + v3.z);
        acc.w += (v0.w + v1.w) + (v2.w + v3.w);
    }
    for (; i < end; ++i) {
        int s = g_col[i];
        float4 v = reinterpret_cast<const float4*>(h + (size_t)s * D)[lane];
        acc.x += v.x; acc.y += v.y; acc.z += v.z; acc.w += v.w;
    }
    float sc = 1.0f / fmaxf((float)(end - beg), 1.0f);
    acc.x *= sc; acc.y *= sc; acc.z *= sc; acc.w *= sc;
    // write swizzled bf16 hi/lo image: lane covers k = lane*4 .. lane*4+3
    int tile = node >> 7;
    int row = node & 127;
    int k0 = lane * 4;
    uint32_t off = (uint32_t)tile * 32768u + (uint32_t)(k0 >> 6) * 16384u
                 + swz((uint32_t)row, (uint32_t)((k0 & 63) * 2));
    uint32_t h0, l0, h1, l1;
    split2(acc.x, acc.y, h0, l0);
    split2(acc.z, acc.w, h1, l1);
    *(uint2*)(nhi + off) = make_uint2(h0, h1);
    *(uint2*)(nlo + off) = make_uint2(l0, l1);
}

// ==================== weight prep: W[k][n] -> swizzled k-major W^T hi/lo images ====
__global__ void prep_weights(const float* W0s, const float* W0n, const float* W1s,
                             const float* W1n, const float* W2s, const float* W2n) {
    const float* Wp[6] = {W0s, W0n, W1s, W1n, W2s, W2n};
    int mat = blockIdx.x >> 3;
    int sub = blockIdx.x & 7;
    const float* W = Wp[mat];
    char* hi = (char*)g_Bimg[mat][0];
    char* lo = (char*)g_Bimg[mat][1];
    for (int t = threadIdx.x; t < 1024; t += blockDim.x) {
        int idx = sub * 1024 + t;          // 0..8191
        int n = idx >> 6;
        int k = (idx & 63) * 2;
        float a0 = W[(size_t)k * D + n];
        float a1 = W[(size_t)(k + 1) * D + n];
        uint32_t hp, lp;
        split2(a0, a1, hp, lp);
        uint32_t off = (uint32_t)(k >> 6) * 16384u + swz((uint32_t)n, (uint32_t)((k & 63) * 2));
        *(uint32_t*)(hi + off) = hp;
        *(uint32_t*)(lo + off) = lp;
    }
}

// ==================== HMMA dual GEMM from pre-swizzled images ====================
__global__ void __launch_bounds__(256, 2)
gemm_hmma_kernel(const char* __restrict__ imgAh, const char* __restrict__ imgAl,
                 const char* __restrict__ imgNh, const char* __restrict__ imgNl,
                 const char* __restrict__ Bs, const char* __restrict__ Bn,  // hi; lo at +32768
                 const float* __restrict__ bias, float* __restrict__ out,
                 char* __restrict__ oImgH, char* __restrict__ oImgL,
                 int relu, int write_img) {
    extern __shared__ char dyn_smem[];
    uint32_t sbase = (smem_u32(dyn_smem) + 127u) & ~127u;
    const uint32_t sAh = sbase;
    const uint32_t sAl = sbase + 16384;
    const uint32_t sBh = sbase + 32768;
    const uint32_t sBl = sbase + 49152;

    const int tid = threadIdx.x;
    const int wid = tid >> 5;
    const int lane = tid & 31;
    const int tile = blockIdx.x;
    const int m0 = tile * 128;
    const int wm = (wid >> 2) * 64;
    const int wn = (wid & 3) * 32;

    float acc[4][4][4];
    #pragma unroll
    for (int i = 0; i < 4; i++)
        #pragma unroll
        for (int j = 0; j < 4; j++)
            #pragma unroll
            for (int r = 0; r < 4; r++) acc[i][j][r] = 0.f;

    #pragma unroll 1
    for (int part = 0; part < 2; ++part) {
        const char* Ah = (part ? imgNh : imgAh) + (size_t)tile * 32768;
        const char* Al = (part ? imgNl : imgAl) + (size_t)tile * 32768;
        const char* Bh = part ? Bn : Bs;
        #pragma unroll 1
        for (int kc = 0; kc < 2; ++kc) {
            __syncthreads();   // previous compute done before overwrite
            const char* srcAh = Ah + kc * 16384;
            const char* srcAl = Al + kc * 16384;
            const char* srcBh = Bh + kc * 16384;
            const char* srcBl = Bh + 32768 + kc * 16384;
            #pragma unroll
            for (int i = 0; i < 4; ++i) {
                uint32_t o = (uint32_t)(tid + i * 256) * 16u;
                cp_async16(sAh + o, srcAh + o);
                cp_async16(sAl + o, srcAl + o);
                cp_async16(sBh + o, srcBh + o);
                cp_async16(sBl + o, srcBl + o);
            }
            CP_COMMIT();
            CP_WAIT0();
            __syncthreads();

            const uint32_t aSel[3] = {sAh, sAh, sAl};
            const uint32_t bSel[3] = {sBh, sBl, sBh};
            #pragma unroll
            for (int c = 0; c < 3; ++c) {
                const uint32_t ab = aSel[c];
                const uint32_t bb = bSel[c];
                #pragma unroll
                for (int ks = 0; ks < 4; ++ks) {
                    uint32_t a[4][4];
                    #pragma unroll
                    for (int i = 0; i < 4; ++i) {
                        uint32_t row = wm + i * 16 + (lane & 15);
                        uint32_t kbyte = ks * 32 + ((lane >> 4) << 4);
                        ldsm_x4(ab + swz(row, kbyte), a[i][0], a[i][1], a[i][2], a[i][3]);
                    }
                    uint32_t b[4][2];
                    #pragma unroll
                    for (int jj = 0; jj < 2; ++jj) {
                        uint32_t mi = (uint32_t)lane >> 3;
                        uint32_t row = wn + jj * 16 + ((mi >> 1) << 3) + (lane & 7);
                        uint32_t kbyte = ks * 32 + ((mi & 1) << 4);
                        uint32_t r0, r1, r2, r3;
                        ldsm_x4(bb + swz(row, kbyte), r0, r1, r2, r3);
                        b[jj * 2 + 0][0] = r0; b[jj * 2 + 0][1] = r1;
                        b[jj * 2 + 1][0] = r2; b[jj * 2 + 1][1] = r3;
                    }
                    #pragma unroll
                    for (int i = 0; i < 4; ++i)
                        #pragma unroll
                        for (int j = 0; j < 4; ++j)
                            mma_16816(acc[i][j], a[i], b[j]);
                }
            }
        }
    }

    // ---- epilogue: bias + relu; fp32 out + optional next-layer images ----
    #pragma unroll
    for (int i = 0; i < 4; ++i) {
        int rloc0 = wm + i * 16 + (lane >> 2);
        int r0 = m0 + rloc0;
        #pragma unroll
        for (int j = 0; j < 4; ++j) {
            int col = wn + j * 8 + (lane & 3) * 2;
            float bx = bias[col], by = bias[col + 1];
            float2 v0 = make_float2(acc[i][j][0] + bx, acc[i][j][1] + by);
            float2 v1 = make_float2(acc[i][j][2] + bx, acc[i][j][3] + by);
            if (relu) {
                v0.x = fmaxf(v0.x, 0.f); v0.y = fmaxf(v0.y, 0.f);
                v1.x = fmaxf(v1.x, 0.f); v1.y = fmaxf(v1.y, 0.f);
            }
            if (r0 < N_NODES)
                *reinterpret_cast<float2*>(out + (size_t)r0 * D + col) = v0;
            if (r0 + 8 < N_NODES)
                *reinterpret_cast<float2*>(out + (size_t)(r0 + 8) * D + col) = v1;
            if (write_img) {
                uint32_t obase = (uint32_t)tile * 32768u + (uint32_t)(col >> 6) * 16384u;
                uint32_t kb = (uint32_t)((col & 63) * 2);
                uint32_t hp, lp;
                if (r0 < N_NODES) {
                    split2(v0.x, v0.y, hp, lp);
                    uint32_t off = obase + swz((uint32_t)rloc0, kb);
                    *(uint32_t*)(oImgH + off) = hp;
                    *(uint32_t*)(oImgL + off) = lp;
                }
                if (r0 + 8 < N_NODES) {
                    split2(v1.x, v1.y, hp, lp);
                    uint32_t off = obase + swz((uint32_t)(rloc0 + 8), kb);
                    *(uint32_t*)(oImgH + off) = hp;
                    *(uint32_t*)(oImgL + off) = lp;
                }
            }
        }
    }
}

// ==================== launch ====================
extern "C" void kernel_launch(void* const* d_in, const int* in_sizes, int n_in,
                              void* d_out, int out_size) {
    const float* features = (const float*)d_in[0];
    const int* src = (const int*)d_in[1];
    const int* dst = (const int*)d_in[2];
    const float* Ws[3] = {(const float*)d_in[3], (const float*)d_in[6], (const float*)d_in[9]};
    const float* Wn[3] = {(const float*)d_in[4], (const float*)d_in[7], (const float*)d_in[10]};
    const float* bb[3] = {(const float*)d_in[5], (const float*)d_in[8], (const float*)d_in[11]};
    float* out = (float*)d_out;

    void *p_h0, *p_h1, *p_hist, *p_bimg, *p_imgA, *p_imgN;
    cudaGetSymbolAddress(&p_h0, g_hbuf0);
    cudaGetSymbolAddress(&p_h1, g_hbuf1);
    cudaGetSymbolAddress(&p_hist, g_hist);
    cudaGetSymbolAddress(&p_bimg, g_Bimg);
    cudaGetSymbolAddress(&p_imgA, g_imgA);
    cudaGetSymbolAddress(&p_imgN, g_imgN);

    char* bimg = (char*)p_bimg;
    auto wimg = [&](int mat) { return bimg + (size_t)mat * 65536; };  // hi; lo at +32768
    const size_t ISZ = (size_t)NT * 32768;  // bytes per image
    char* aimg = (char*)p_imgA;
    auto aimgp = [&](int set, int part) { return aimg + ((size_t)set * 2 + part) * ISZ; };
    char* nimg = (char*)p_imgN;

    const size_t smem_bytes = 65536 + 128;
    cudaFuncSetAttribute(gemm_hmma_kernel, cudaFuncAttributeMaxDynamicSharedMemorySize,
                         (int)smem_bytes);

    // prep: CSR + feature images + weight images
    cudaMemsetAsync(p_hist, 0, N_NODES * sizeof(int));
    hist_kernel<<<(N_EDGES + 255) / 256, 256>>>(dst);
    convert_features<<<NT, 256>>>(features, aimgp(0, 0), aimgp(0, 1));
    prep_weights<<<48, 256>>>(Ws[0], Wn[0], Ws[1], Wn[1], Ws[2], Wn[2]);
    scan_local<<<SCAN_BLOCKS, 256>>>();
    scan_blocks<<<1, 256>>>();
    scan_apply<<<SCAN_BLOCKS, 256>>>();
    fill_kernel<<<(N_EDGES + 255) / 256, 256>>>(src, dst);

    const float* hin = features;
    float* bufs[3] = {(float*)p_h0, (float*)p_h1, out};
    for (int l = 0; l < 3; ++l) {
        int rset = l & 1;            // 0,1,0
        int wset = 1 - rset;
        aggregate_kernel<<<(N_NODES * 32 + 255) / 256, 256>>>(hin, nimg, nimg + ISZ);
        gemm_hmma_kernel<<<NT, 256, smem_bytes>>>(
            aimgp(rset, 0), aimgp(rset, 1), nimg, nimg + ISZ,
            wimg(l * 2 + 0), wimg(l * 2 + 1), bb[l], bufs[l],
            aimgp(wset, 0), aimgp(wset, 1), (l < 2) ? 1 : 0, (l < 2) ? 1 : 0);
        hin = bufs[l];
    }
}

// round 7
// speedup vs baseline: 4.4445x; 1.1528x over previous
#include <cuda_runtime.h>
#include <cuda_bf16.h>
#include <cstdint>

#define N_NODES 50000
#define N_EDGES 800000
#define D 128
#define NT 391            // ceil(N_NODES/128)
#define SCAN_BLOCKS 196   // 196*256 = 50176 >= N_NODES

// ==================== scratch (no allocations allowed) ====================
__device__ float g_hbuf0[(size_t)N_NODES * D];
__device__ float g_hbuf1[(size_t)N_NODES * D];
__device__ int g_hist[N_NODES];
__device__ int g_cursor[N_NODES];
__device__ int g_rowstart[N_NODES + 1];
__device__ int g_col[N_EDGES];
__device__ int g_blocksum[SCAN_BLOCKS];
__device__ int g_blockoff[SCAN_BLOCKS];
// pre-swizzled bf16 W^T images: [matrix 0..5][hi=0/lo=1][2 kchunks x 128 x 64]
__device__ __align__(128) __nv_bfloat16 g_Bimg[6][2][D * D];
// node-feature tile images: [set][hi/lo][tile*16384 bf16] (32KB per tile: kc0|kc1)
__device__ __align__(128) __nv_bfloat16 g_imgA[2][2][(size_t)NT * 16384];
// hneigh tile images: [hi/lo]
__device__ __align__(128) __nv_bfloat16 g_imgN[2][(size_t)NT * 16384];

// XOR swizzle: row-major 64 bf16 per row (128B), 8 chunks of 16B, chunk ^= row&7
__device__ __forceinline__ uint32_t swz(uint32_t row, uint32_t kbyte) {
    return row * 128u + ((((kbyte >> 4) ^ (row & 7u)) << 4) | (kbyte & 15u));
}

__device__ __forceinline__ uint32_t smem_u32(const void* p) {
    uint32_t a;
    asm("{ .reg .u64 t; cvta.to.shared.u64 t, %1; cvt.u32.u64 %0, t; }" : "=r"(a) : "l"(p));
    return a;
}
__device__ __forceinline__ void cp_async16(uint32_t saddr, const void* gptr) {
    asm volatile("cp.async.cg.shared.global [%0], [%1], 16;" :: "r"(saddr), "l"(gptr));
}
#define CP_COMMIT() asm volatile("cp.async.commit_group;" ::: "memory")
#define CP_WAIT(n)  asm volatile("cp.async.wait_group %0;" :: "n"(n) : "memory")

__device__ __forceinline__ void ldsm_x4(uint32_t addr, uint32_t& r0, uint32_t& r1,
                                        uint32_t& r2, uint32_t& r3) {
    asm volatile("ldmatrix.sync.aligned.m8n8.x4.shared.b16 {%0,%1,%2,%3}, [%4];"
                 : "=r"(r0), "=r"(r1), "=r"(r2), "=r"(r3) : "r"(addr));
}
__device__ __forceinline__ void mma_16816(float* c, const uint32_t* a, const uint32_t* b) {
    asm volatile(
        "mma.sync.aligned.m16n8k16.row.col.f32.bf16.bf16.f32 "
        "{%0,%1,%2,%3}, {%4,%5,%6,%7}, {%8,%9}, {%0,%1,%2,%3};"
        : "+f"(c[0]), "+f"(c[1]), "+f"(c[2]), "+f"(c[3])
        : "r"(a[0]), "r"(a[1]), "r"(a[2]), "r"(a[3]), "r"(b[0]), "r"(b[1]));
}
// split x,y into packed bf16x2 hi + bf16x2 lo(residual)
__device__ __forceinline__ void split2(float x, float y, uint32_t& hp, uint32_t& lp) {
    __nv_bfloat16 hx = __float2bfloat16(x);
    __nv_bfloat16 hy = __float2bfloat16(y);
    __nv_bfloat16 lx = __float2bfloat16(x - __bfloat162float(hx));
    __nv_bfloat16 ly = __float2bfloat16(y - __bfloat162float(hy));
    hp = (uint32_t)__bfloat16_as_ushort(hx) | ((uint32_t)__bfloat16_as_ushort(hy) << 16);
    lp = (uint32_t)__bfloat16_as_ushort(lx) | ((uint32_t)__bfloat16_as_ushort(ly) << 16);
}

// ==================== CSR build ====================
__global__ void hist_kernel(const int* __restrict__ dst) {
    int e = blockIdx.x * blockDim.x + threadIdx.x;
    if (e < N_EDGES) atomicAdd(&g_hist[dst[e]], 1);
}

__global__ void scan_local() {
    __shared__ int sh[256];
    int t = threadIdx.x;
    int idx = blockIdx.x * 256 + t;
    int v = (idx < N_NODES) ? g_hist[idx] : 0;
    sh[t] = v;
    __syncthreads();
    #pragma unroll
    for (int off = 1; off < 256; off <<= 1) {
        int x = sh[t];
        int add = (t >= off) ? sh[t - off] : 0;
        __syncthreads();
        sh[t] = x + add;
        __syncthreads();
    }
    if (idx < N_NODES) g_rowstart[idx] = sh[t] - v;
    if (t == 255) g_blocksum[blockIdx.x] = sh[255];
}

__global__ void scan_blocks() {
    __shared__ int sh[256];
    int t = threadIdx.x;
    int v = (t < SCAN_BLOCKS) ? g_blocksum[t] : 0;
    sh[t] = v;
    __syncthreads();
    #pragma unroll
    for (int off = 1; off < 256; off <<= 1) {
        int x = sh[t];
        int add = (t >= off) ? sh[t - off] : 0;
        __syncthreads();
        sh[t] = x + add;
        __syncthreads();
    }
    if (t < SCAN_BLOCKS) g_blockoff[t] = sh[t] - v;
    if (t == 255) g_rowstart[N_NODES] = sh[255];
}

__global__ void scan_apply() {
    int idx = blockIdx.x * 256 + threadIdx.x;
    if (idx < N_NODES) {
        int r = g_rowstart[idx] + g_blockoff[blockIdx.x];
        g_rowstart[idx] = r;
        g_cursor[idx] = r;
    }
}

__global__ void fill_kernel(const int* __restrict__ src, const int* __restrict__ dst) {
    int e = blockIdx.x * blockDim.x + threadIdx.x;
    if (e < N_EDGES) {
        int pos = atomicAdd(&g_cursor[dst[e]], 1);
        g_col[pos] = src[e];
    }
}

// ==================== features fp32 -> tile images (set 0) ====================
__global__ void convert_features(const float* __restrict__ h, char* __restrict__ hi,
                                 char* __restrict__ lo) {
    int tile = blockIdx.x;
    int m0 = tile * 128;
    #pragma unroll 4
    for (int it = 0; it < 32; ++it) {
        int idx = threadIdx.x + it * 256;
        int row = idx >> 6;
        int k = (idx & 63) * 2;
        int gm = m0 + row;
        float2 a = (gm < N_NODES) ? *reinterpret_cast<const float2*>(h + (size_t)gm * D + k)
                                  : make_float2(0.f, 0.f);
        uint32_t hp, lp;
        split2(a.x, a.y, hp, lp);
        uint32_t off = (uint32_t)tile * 32768u + (uint32_t)(k >> 6) * 16384u
                     + swz((uint32_t)row, (uint32_t)((k & 63) * 2));
        *(uint32_t*)(hi + off) = hp;
        *(uint32_t*)(lo + off) = lp;
    }
}

// ==================== aggregation: warp/node -> hneigh images directly ============
__global__ void aggregate_kernel(const float* __restrict__ h, char* __restrict__ nhi,
                                 char* __restrict__ nlo) {
    int node = (blockIdx.x * blockDim.x + threadIdx.x) >> 5;
    int lane = threadIdx.x & 31;
    if (node >= N_NODES) return;
    int beg = g_rowstart[node];
    int end = g_rowstart[node + 1];
    float4 acc = make_float4(0.f, 0.f, 0.f, 0.f);
    int i = beg;
    for (; i + 4 <= end; i += 4) {
        int s0 = g_col[i + 0];
        int s1 = g_col[i + 1];
        int s2 = g_col[i + 2];
        int s3 = g_col[i + 3];
        float4 v0 = reinterpret_cast<const float4*>(h + (size_t)s0 * D)[lane];
        float4 v1 = reinterpret_cast<const float4*>(h + (size_t)s1 * D)[lane];
        float4 v2 = reinterpret_cast<const float4*>(h + (size_t)s2 * D)[lane];
        float4 v3 = reinterpret_cast<const float4*>(h + (size_t)s3 * D)[lane];
        acc.x += (v0.x + v1.x) + (v2.x + v3.x);
        acc.y += (v0.y + v1.y) + (v2.y + v3.y);
        acc.z += (v0.z + v1.z) + (v2.z + v3.z);
        acc.w += (v0.w + v1.w) + (v2.w + v3.w);
    }
    for (; i < end; ++i) {
        int s = g_col[i];
        float4 v = reinterpret_cast<const float4*>(h + (size_t)s * D)[lane];
        acc.x += v.x; acc.y += v.y; acc.z += v.z; acc.w += v.w;
    }
    float sc = 1.0f / fmaxf((float)(end - beg), 1.0f);
    acc.x *= sc; acc.y *= sc; acc.z *= sc; acc.w *= sc;
    int tile = node >> 7;
    int row = node & 127;
    int k0 = lane * 4;
    uint32_t off = (uint32_t)tile * 32768u + (uint32_t)(k0 >> 6) * 16384u
                 + swz((uint32_t)row, (uint32_t)((k0 & 63) * 2));
    uint32_t h0, l0, h1, l1;
    split2(acc.x, acc.y, h0, l0);
    split2(acc.z, acc.w, h1, l1);
    *(uint2*)(nhi + off) = make_uint2(h0, h1);
    *(uint2*)(nlo + off) = make_uint2(l0, l1);
}

// ==================== weight prep ====================
__global__ void prep_weights(const float* W0s, const float* W0n, const float* W1s,
                             const float* W1n, const float* W2s, const float* W2n) {
    const float* Wp[6] = {W0s, W0n, W1s, W1n, W2s, W2n};
    int mat = blockIdx.x >> 3;
    int sub = blockIdx.x & 7;
    const float* W = Wp[mat];
    char* hi = (char*)g_Bimg[mat][0];
    char* lo = (char*)g_Bimg[mat][1];
    for (int t = threadIdx.x; t < 1024; t += blockDim.x) {
        int idx = sub * 1024 + t;
        int n = idx >> 6;
        int k = (idx & 63) * 2;
        float a0 = W[(size_t)k * D + n];
        float a1 = W[(size_t)(k + 1) * D + n];
        uint32_t hp, lp;
        split2(a0, a1, hp, lp);
        uint32_t off = (uint32_t)(k >> 6) * 16384u + swz((uint32_t)n, (uint32_t)((k & 63) * 2));
        *(uint32_t*)(hi + off) = hp;
        *(uint32_t*)(lo + off) = lp;
    }
}

// ==================== HMMA dual GEMM, double-buffered cp.async pipeline ============
__global__ void __launch_bounds__(256, 1)
gemm_hmma_kernel(const char* __restrict__ imgAh, const char* __restrict__ imgAl,
                 const char* __restrict__ imgNh, const char* __restrict__ imgNl,
                 const char* __restrict__ Bs, const char* __restrict__ Bn,  // hi; lo at +32768
                 const float* __restrict__ bias, float* __restrict__ out,
                 char* __restrict__ oImgH, char* __restrict__ oImgL,
                 int relu, int write_img) {
    extern __shared__ char dyn_smem[];
    uint32_t sbase = (smem_u32(dyn_smem) + 127u) & ~127u;

    const int tid = threadIdx.x;
    const int wid = tid >> 5;
    const int lane = tid & 31;
    const int tile = blockIdx.x;
    const int m0 = tile * 128;
    const int wm = (wid >> 2) * 64;
    const int wn = (wid & 3) * 32;

    // phase p = (part<<1)|kc : source pointers for Ah/Al/Bh/Bl (16KB each)
    const char* srcAh[4];
    const char* srcAl[4];
    const char* srcBh[4];
    const char* srcBl[4];
    {
        const char* Ah0 = imgAh + (size_t)tile * 32768;
        const char* Al0 = imgAl + (size_t)tile * 32768;
        const char* Nh0 = imgNh + (size_t)tile * 32768;
        const char* Nl0 = imgNl + (size_t)tile * 32768;
        #pragma unroll
        for (int kc = 0; kc < 2; ++kc) {
            srcAh[kc] = Ah0 + kc * 16384;  srcAh[2 + kc] = Nh0 + kc * 16384;
            srcAl[kc] = Al0 + kc * 16384;  srcAl[2 + kc] = Nl0 + kc * 16384;
            srcBh[kc] = Bs + kc * 16384;   srcBh[2 + kc] = Bn + kc * 16384;
            srcBl[kc] = Bs + 32768 + kc * 16384;
            srcBl[2 + kc] = Bn + 32768 + kc * 16384;
        }
    }

    // stage phase p into buffer b (64KB each: Ah|Al|Bh|Bl)
    auto stage = [&](int p, int b) {
        uint32_t sb = sbase + (uint32_t)b * 65536u;
        #pragma unroll
        for (int i = 0; i < 4; ++i) {
            uint32_t o = (uint32_t)(tid + i * 256) * 16u;
            cp_async16(sb + o, srcAh[p] + o);
            cp_async16(sb + 16384 + o, srcAl[p] + o);
            cp_async16(sb + 32768 + o, srcBh[p] + o);
            cp_async16(sb + 49152 + o, srcBl[p] + o);
        }
        CP_COMMIT();
    };

    float acc[4][4][4];
    #pragma unroll
    for (int i = 0; i < 4; i++)
        #pragma unroll
        for (int j = 0; j < 4; j++)
            #pragma unroll
            for (int r = 0; r < 4; r++) acc[i][j][r] = 0.f;

    stage(0, 0);

    #pragma unroll 1
    for (int p = 0; p < 4; ++p) {
        if (p < 3) stage(p + 1, (p + 1) & 1);
        if (p < 3) { CP_WAIT(1); } else { CP_WAIT(0); }
        __syncthreads();

        uint32_t sb = sbase + (uint32_t)(p & 1) * 65536u;
        const uint32_t sAh = sb, sAl = sb + 16384, sBh = sb + 32768, sBl = sb + 49152;
        const uint32_t aSel[3] = {sAh, sAh, sAl};
        const uint32_t bSel[3] = {sBh, sBl, sBh};
        #pragma unroll
        for (int c = 0; c < 3; ++c) {
            const uint32_t ab = aSel[c];
            const uint32_t bb = bSel[c];
            #pragma unroll
            for (int ks = 0; ks < 4; ++ks) {
                uint32_t a[4][4];
                #pragma unroll
                for (int i = 0; i < 4; ++i) {
                    uint32_t row = wm + i * 16 + (lane & 15);
                    uint32_t kbyte = ks * 32 + ((lane >> 4) << 4);
                    ldsm_x4(ab + swz(row, kbyte), a[i][0], a[i][1], a[i][2], a[i][3]);
                }
                uint32_t b[4][2];
                #pragma unroll
                for (int jj = 0; jj < 2; ++jj) {
                    uint32_t mi = (uint32_t)lane >> 3;
                    uint32_t row = wn + jj * 16 + ((mi >> 1) << 3) + (lane & 7);
                    uint32_t kbyte = ks * 32 + ((mi & 1) << 4);
                    uint32_t r0, r1, r2, r3;
                    ldsm_x4(bb + swz(row, kbyte), r0, r1, r2, r3);
                    b[jj * 2 + 0][0] = r0; b[jj * 2 + 0][1] = r1;
                    b[jj * 2 + 1][0] = r2; b[jj * 2 + 1][1] = r3;
                }
                #pragma unroll
                for (int i = 0; i < 4; ++i)
                    #pragma unroll
                    for (int j = 0; j < 4; ++j)
                        mma_16816(acc[i][j], a[i], b[j]);
            }
        }
        __syncthreads();   // all warps done reading buf before it is overwritten at p+2
    }

    // ---- epilogue: bias + relu; fp32 out + optional next-layer images ----
    #pragma unroll
    for (int i = 0; i < 4; ++i) {
        int rloc0 = wm + i * 16 + (lane >> 2);
        int r0 = m0 + rloc0;
        #pragma unroll
        for (int j = 0; j < 4; ++j) {
            int col = wn + j * 8 + (lane & 3) * 2;
            float bx = bias[col], by = bias[col + 1];
            float2 v0 = make_float2(acc[i][j][0] + bx, acc[i][j][1] + by);
            float2 v1 = make_float2(acc[i][j][2] + bx, acc[i][j][3] + by);
            if (relu) {
                v0.x = fmaxf(v0.x, 0.f); v0.y = fmaxf(v0.y, 0.f);
                v1.x = fmaxf(v1.x, 0.f); v1.y = fmaxf(v1.y, 0.f);
            }
            if (r0 < N_NODES)
                *reinterpret_cast<float2*>(out + (size_t)r0 * D + col) = v0;
            if (r0 + 8 < N_NODES)
                *reinterpret_cast<float2*>(out + (size_t)(r0 + 8) * D + col) = v1;
            if (write_img) {
                uint32_t obase = (uint32_t)tile * 32768u + (uint32_t)(col >> 6) * 16384u;
                uint32_t kb = (uint32_t)((col & 63) * 2);
                uint32_t hp, lp;
                if (r0 < N_NODES) {
                    split2(v0.x, v0.y, hp, lp);
                    uint32_t off = obase + swz((uint32_t)rloc0, kb);
                    *(uint32_t*)(oImgH + off) = hp;
                    *(uint32_t*)(oImgL + off) = lp;
                }
                if (r0 + 8 < N_NODES) {
                    split2(v1.x, v1.y, hp, lp);
                    uint32_t off = obase + swz((uint32_t)(rloc0 + 8), kb);
                    *(uint32_t*)(oImgH + off) = hp;
                    *(uint32_t*)(oImgL + off) = lp;
                }
            }
        }
    }
}

// ==================== launch ====================
extern "C" void kernel_launch(void* const* d_in, const int* in_sizes, int n_in,
                              void* d_out, int out_size) {
    const float* features = (const float*)d_in[0];
    const int* src = (const int*)d_in[1];
    const int* dst = (const int*)d_in[2];
    const float* Ws[3] = {(const float*)d_in[3], (const float*)d_in[6], (const float*)d_in[9]};
    const float* Wn[3] = {(const float*)d_in[4], (const float*)d_in[7], (const float*)d_in[10]};
    const float* bb[3] = {(const float*)d_in[5], (const float*)d_in[8], (const float*)d_in[11]};
    float* out = (float*)d_out;

    void *p_h0, *p_h1, *p_hist, *p_bimg, *p_imgA, *p_imgN;
    cudaGetSymbolAddress(&p_h0, g_hbuf0);
    cudaGetSymbolAddress(&p_h1, g_hbuf1);
    cudaGetSymbolAddress(&p_hist, g_hist);
    cudaGetSymbolAddress(&p_bimg, g_Bimg);
    cudaGetSymbolAddress(&p_imgA, g_imgA);
    cudaGetSymbolAddress(&p_imgN, g_imgN);

    char* bimg = (char*)p_bimg;
    auto wimg = [&](int mat) { return bimg + (size_t)mat * 65536; };
    const size_t ISZ = (size_t)NT * 32768;
    char* aimg = (char*)p_imgA;
    auto aimgp = [&](int set, int part) { return aimg + ((size_t)set * 2 + part) * ISZ; };
    char* nimg = (char*)p_imgN;

    const size_t smem_bytes = 2 * 65536 + 128;
    cudaFuncSetAttribute(gemm_hmma_kernel, cudaFuncAttributeMaxDynamicSharedMemorySize,
                         (int)smem_bytes);

    cudaMemsetAsync(p_hist, 0, N_NODES * sizeof(int));
    hist_kernel<<<(N_EDGES + 255) / 256, 256>>>(dst);
    convert_features<<<NT, 256>>>(features, aimgp(0, 0), aimgp(0, 1));
    prep_weights<<<48, 256>>>(Ws[0], Wn[0], Ws[1], Wn[1], Ws[2], Wn[2]);
    scan_local<<<SCAN_BLOCKS, 256>>>();
    scan_blocks<<<1, 256>>>();
    scan_apply<<<SCAN_BLOCKS, 256>>>();
    fill_kernel<<<(N_EDGES + 255) / 256, 256>>>(src, dst);

    const float* hin = features;
    float* bufs[3] = {(float*)p_h0, (float*)p_h1, out};
    for (int l = 0; l < 3; ++l) {
        int rset = l & 1;
        int wset = 1 - rset;
        aggregate_kernel<<<(N_NODES * 32 + 255) / 256, 256>>>(hin, nimg, nimg + ISZ);
        gemm_hmma_kernel<<<NT, 256, smem_bytes>>>(
            aimgp(rset, 0), aimgp(rset, 1), nimg, nimg + ISZ,
            wimg(l * 2 + 0), wimg(l * 2 + 1), bb[l], bufs[l],
            aimgp(wset, 0), aimgp(wset, 1), (l < 2) ? 1 : 0, (l < 2) ? 1 : 0);
        hin = bufs[l];
    }
}

// round 8
// speedup vs baseline: 4.5966x; 1.0342x over previous
#include <cuda_runtime.h>
#include <cuda_bf16.h>
#include <cstdint>

#define N_NODES 50000
#define N_EDGES 800000
#define D 128
#define NT 391            // ceil(N_NODES/128)
#define SCAN_BLOCKS 196   // 196*256 = 50176 >= N_NODES

// ==================== scratch (no allocations allowed) ====================
__device__ float g_hbuf0[(size_t)N_NODES * D];
__device__ float g_hbuf1[(size_t)N_NODES * D];
__device__ int g_hist[N_NODES];
__device__ int g_cursor[N_NODES];
__device__ int g_rowstart[N_NODES + 1];
__device__ int g_col[N_EDGES];
__device__ int g_blocksum[SCAN_BLOCKS];
__device__ int g_blockoff[SCAN_BLOCKS];
// pre-swizzled bf16 W^T images: [matrix 0..5][hi=0/lo=1][2 kchunks x 128 x 64]
__device__ __align__(128) __nv_bfloat16 g_Bimg[6][2][D * D];
// node-feature tile images: [set][hi/lo][tile*16384 bf16] (32KB per tile: kc0|kc1)
__device__ __align__(128) __nv_bfloat16 g_imgA[2][2][(size_t)NT * 16384];
// hneigh tile images: [hi/lo]
__device__ __align__(128) __nv_bfloat16 g_imgN[2][(size_t)NT * 16384];

// XOR swizzle: row-major 64 bf16 per row (128B), 8 chunks of 16B, chunk ^= row&7
__device__ __forceinline__ uint32_t swz(uint32_t row, uint32_t kbyte) {
    return row * 128u + ((((kbyte >> 4) ^ (row & 7u)) << 4) | (kbyte & 15u));
}

__device__ __forceinline__ uint32_t smem_u32(const void* p) {
    uint32_t a;
    asm("{ .reg .u64 t; cvta.to.shared.u64 t, %1; cvt.u32.u64 %0, t; }" : "=r"(a) : "l"(p));
    return a;
}
__device__ __forceinline__ void cp_async16(uint32_t saddr, const void* gptr) {
    asm volatile("cp.async.cg.shared.global [%0], [%1], 16;" :: "r"(saddr), "l"(gptr));
}
#define CP_COMMIT() asm volatile("cp.async.commit_group;" ::: "memory")
#define CP_WAIT(n)  asm volatile("cp.async.wait_group %0;" :: "n"(n) : "memory")

__device__ __forceinline__ void ldsm_x4(uint32_t addr, uint32_t& r0, uint32_t& r1,
                                        uint32_t& r2, uint32_t& r3) {
    asm volatile("ldmatrix.sync.aligned.m8n8.x4.shared.b16 {%0,%1,%2,%3}, [%4];"
                 : "=r"(r0), "=r"(r1), "=r"(r2), "=r"(r3) : "r"(addr));
}
__device__ __forceinline__ void mma_16816(float* c, const uint32_t* a, const uint32_t* b) {
    asm volatile(
        "mma.sync.aligned.m16n8k16.row.col.f32.bf16.bf16.f32 "
        "{%0,%1,%2,%3}, {%4,%5,%6,%7}, {%8,%9}, {%0,%1,%2,%3};"
        : "+f"(c[0]), "+f"(c[1]), "+f"(c[2]), "+f"(c[3])
        : "r"(a[0]), "r"(a[1]), "r"(a[2]), "r"(a[3]), "r"(b[0]), "r"(b[1]));
}
// split x,y into packed bf16x2 hi + bf16x2 lo(residual)
__device__ __forceinline__ void split2(float x, float y, uint32_t& hp, uint32_t& lp) {
    __nv_bfloat16 hx = __float2bfloat16(x);
    __nv_bfloat16 hy = __float2bfloat16(y);
    __nv_bfloat16 lx = __float2bfloat16(x - __bfloat162float(hx));
    __nv_bfloat16 ly = __float2bfloat16(y - __bfloat162float(hy));
    hp = (uint32_t)__bfloat16_as_ushort(hx) | ((uint32_t)__bfloat16_as_ushort(hy) << 16);
    lp = (uint32_t)__bfloat16_as_ushort(lx) | ((uint32_t)__bfloat16_as_ushort(ly) << 16);
}

// ==================== CSR build ====================
__global__ void hist_kernel(const int* __restrict__ dst) {
    int e = blockIdx.x * blockDim.x + threadIdx.x;
    if (e < N_EDGES) atomicAdd(&g_hist[dst[e]], 1);
}

__global__ void scan_local() {
    __shared__ int sh[256];
    int t = threadIdx.x;
    int idx = blockIdx.x * 256 + t;
    int v = (idx < N_NODES) ? g_hist[idx] : 0;
    sh[t] = v;
    __syncthreads();
    #pragma unroll
    for (int off = 1; off < 256; off <<= 1) {
        int x = sh[t];
        int add = (t >= off) ? sh[t - off] : 0;
        __syncthreads();
        sh[t] = x + add;
        __syncthreads();
    }
    if (idx < N_NODES) g_rowstart[idx] = sh[t] - v;
    if (t == 255) g_blocksum[blockIdx.x] = sh[255];
}

__global__ void scan_blocks() {
    __shared__ int sh[256];
    int t = threadIdx.x;
    int v = (t < SCAN_BLOCKS) ? g_blocksum[t] : 0;
    sh[t] = v;
    __syncthreads();
    #pragma unroll
    for (int off = 1; off < 256; off <<= 1) {
        int x = sh[t];
        int add = (t >= off) ? sh[t - off] : 0;
        __syncthreads();
        sh[t] = x + add;
        __syncthreads();
    }
    if (t < SCAN_BLOCKS) g_blockoff[t] = sh[t] - v;
    if (t == 255) g_rowstart[N_NODES] = sh[255];
}

__global__ void scan_apply() {
    int idx = blockIdx.x * 256 + threadIdx.x;
    if (idx < N_NODES) {
        int r = g_rowstart[idx] + g_blockoff[blockIdx.x];
        g_rowstart[idx] = r;
        g_cursor[idx] = r;
    }
}

__global__ void fill_kernel(const int* __restrict__ src, const int* __restrict__ dst) {
    int e = blockIdx.x * blockDim.x + threadIdx.x;
    if (e < N_EDGES) {
        int pos = atomicAdd(&g_cursor[dst[e]], 1);
        g_col[pos] = src[e];
    }
}

// ==================== features fp32 -> tile images (set 0) ====================
__global__ void convert_features(const float* __restrict__ h, char* __restrict__ hi,
                                 char* __restrict__ lo) {
    int tile = blockIdx.x;
    int m0 = tile * 128;
    #pragma unroll 4
    for (int it = 0; it < 32; ++it) {
        int idx = threadIdx.x + it * 256;
        int row = idx >> 6;
        int k = (idx & 63) * 2;
        int gm = m0 + row;
        float2 a = (gm < N_NODES) ? *reinterpret_cast<const float2*>(h + (size_t)gm * D + k)
                                  : make_float2(0.f, 0.f);
        uint32_t hp, lp;
        split2(a.x, a.y, hp, lp);
        uint32_t off = (uint32_t)tile * 32768u + (uint32_t)(k >> 6) * 16384u
                     + swz((uint32_t)row, (uint32_t)((k & 63) * 2));
        *(uint32_t*)(hi + off) = hp;
        *(uint32_t*)(lo + off) = lp;
    }
}

// ==================== aggregation: warp/node -> hneigh images directly ============
__global__ void aggregate_kernel(const float* __restrict__ h, char* __restrict__ nhi,
                                 char* __restrict__ nlo) {
    int node = (blockIdx.x * blockDim.x + threadIdx.x) >> 5;
    int lane = threadIdx.x & 31;
    if (node >= N_NODES) return;
    int beg = g_rowstart[node];
    int end = g_rowstart[node + 1];
    float4 acc = make_float4(0.f, 0.f, 0.f, 0.f);
    int i = beg;
    for (; i + 4 <= end; i += 4) {
        int s0 = g_col[i + 0];
        int s1 = g_col[i + 1];
        int s2 = g_col[i + 2];
        int s3 = g_col[i + 3];
        float4 v0 = reinterpret_cast<const float4*>(h + (size_t)s0 * D)[lane];
        float4 v1 = reinterpret_cast<const float4*>(h + (size_t)s1 * D)[lane];
        float4 v2 = reinterpret_cast<const float4*>(h + (size_t)s2 * D)[lane];
        float4 v3 = reinterpret_cast<const float4*>(h + (size_t)s3 * D)[lane];
        acc.x += (v0.x + v1.x) + (v2.x + v3.x);
        acc.y += (v0.y + v1.y) + (v2.y + v3.y);
        acc.z += (v0.z + v1.z) + (v2.z + v3.z);
        acc.w += (v0.w + v1.w) + (v2.w + v3.w);
    }
    for (; i < end; ++i) {
        int s = g_col[i];
        float4 v = reinterpret_cast<const float4*>(h + (size_t)s * D)[lane];
        acc.x += v.x; acc.y += v.y; acc.z += v.z; acc.w += v.w;
    }
    float sc = 1.0f / fmaxf((float)(end - beg), 1.0f);
    acc.x *= sc; acc.y *= sc; acc.z *= sc; acc.w *= sc;
    int tile = node >> 7;
    int row = node & 127;
    int k0 = lane * 4;
    uint32_t off = (uint32_t)tile * 32768u + (uint32_t)(k0 >> 6) * 16384u
                 + swz((uint32_t)row, (uint32_t)((k0 & 63) * 2));
    uint32_t h0, l0, h1, l1;
    split2(acc.x, acc.y, h0, l0);
    split2(acc.z, acc.w, h1, l1);
    *(uint2*)(nhi + off) = make_uint2(h0, h1);
    *(uint2*)(nlo + off) = make_uint2(l0, l1);
}

// ==================== weight prep ====================
__global__ void prep_weights(const float* W0s, const float* W0n, const float* W1s,
                             const float* W1n, const float* W2s, const float* W2n) {
    const float* Wp[6] = {W0s, W0n, W1s, W1n, W2s, W2n};
    int mat = blockIdx.x >> 3;
    int sub = blockIdx.x & 7;
    const float* W = Wp[mat];
    char* hi = (char*)g_Bimg[mat][0];
    char* lo = (char*)g_Bimg[mat][1];
    for (int t = threadIdx.x; t < 1024; t += blockDim.x) {
        int idx = sub * 1024 + t;
        int n = idx >> 6;
        int k = (idx & 63) * 2;
        float a0 = W[(size_t)k * D + n];
        float a1 = W[(size_t)(k + 1) * D + n];
        uint32_t hp, lp;
        split2(a0, a1, hp, lp);
        uint32_t off = (uint32_t)(k >> 6) * 16384u + swz((uint32_t)n, (uint32_t)((k & 63) * 2));
        *(uint32_t*)(hi + off) = hp;
        *(uint32_t*)(lo + off) = lp;
    }
}

// ==================== HMMA dual GEMM, 12x32KB phases, double-buffered, occ=2 =======
__global__ void __launch_bounds__(256, 2)
gemm_hmma_kernel(const char* __restrict__ imgAh, const char* __restrict__ imgAl,
                 const char* __restrict__ imgNh, const char* __restrict__ imgNl,
                 const char* __restrict__ Bs, const char* __restrict__ Bn,  // hi; lo at +32768
                 const float* __restrict__ bias, float* __restrict__ out,
                 char* __restrict__ oImgH, char* __restrict__ oImgL,
                 int relu, int write_img) {
    extern __shared__ char dyn_smem[];
    uint32_t sbase = (smem_u32(dyn_smem) + 127u) & ~127u;

    const int tid = threadIdx.x;
    const int wid = tid >> 5;
    const int lane = tid & 31;
    const int tile = blockIdx.x;
    const int m0 = tile * 128;
    const int wm = (wid >> 2) * 64;
    const int wn = (wid & 3) * 32;

    // 12 phases: p = part*6 + c*2 + kc. chain c: (Ah,Bh),(Ah,Bl),(Al,Bh).
    const char* srcA[12];
    const char* srcB[12];
    {
        const char* Ahi[2] = {imgAh + (size_t)tile * 32768, imgNh + (size_t)tile * 32768};
        const char* Alo[2] = {imgAl + (size_t)tile * 32768, imgNl + (size_t)tile * 32768};
        const char* Bhi[2] = {Bs, Bn};
        const char* Blo[2] = {Bs + 32768, Bn + 32768};
        #pragma unroll
        for (int part = 0; part < 2; ++part)
            #pragma unroll
            for (int c = 0; c < 3; ++c)
                #pragma unroll
                for (int kc = 0; kc < 2; ++kc) {
                    int p = part * 6 + c * 2 + kc;
                    srcA[p] = (c == 2 ? Alo[part] : Ahi[part]) + kc * 16384;
                    srcB[p] = (c == 1 ? Blo[part] : Bhi[part]) + kc * 16384;
                }
    }

    // stage phase p into buffer b (32KB: A 16KB | B 16KB)
    auto stage = [&](int p, int b) {
        uint32_t sb = sbase + (uint32_t)b * 32768u;
        #pragma unroll
        for (int i = 0; i < 4; ++i) {
            uint32_t o = (uint32_t)(tid + i * 256) * 16u;
            cp_async16(sb + o, srcA[p] + o);
            cp_async16(sb + 16384 + o, srcB[p] + o);
        }
        CP_COMMIT();
    };

    float acc[4][4][4];
    #pragma unroll
    for (int i = 0; i < 4; i++)
        #pragma unroll
        for (int j = 0; j < 4; j++)
            #pragma unroll
            for (int r = 0; r < 4; r++) acc[i][j][r] = 0.f;

    stage(0, 0);

    #pragma unroll 1
    for (int p = 0; p < 12; ++p) {
        if (p < 11) stage(p + 1, (p + 1) & 1);
        if (p < 11) { CP_WAIT(1); } else { CP_WAIT(0); }
        __syncthreads();

        uint32_t sb = sbase + (uint32_t)(p & 1) * 32768u;
        const uint32_t sA = sb, sB = sb + 16384;
        #pragma unroll
        for (int ks = 0; ks < 4; ++ks) {
            uint32_t a[4][4];
            #pragma unroll
            for (int i = 0; i < 4; ++i) {
                uint32_t row = wm + i * 16 + (lane & 15);
                uint32_t kbyte = ks * 32 + ((lane >> 4) << 4);
                ldsm_x4(sA + swz(row, kbyte), a[i][0], a[i][1], a[i][2], a[i][3]);
            }
            uint32_t b[4][2];
            #pragma unroll
            for (int jj = 0; jj < 2; ++jj) {
                uint32_t mi = (uint32_t)lane >> 3;
                uint32_t row = wn + jj * 16 + ((mi >> 1) << 3) + (lane & 7);
                uint32_t kbyte = ks * 32 + ((mi & 1) << 4);
                uint32_t r0, r1, r2, r3;
                ldsm_x4(sB + swz(row, kbyte), r0, r1, r2, r3);
                b[jj * 2 + 0][0] = r0; b[jj * 2 + 0][1] = r1;
                b[jj * 2 + 1][0] = r2; b[jj * 2 + 1][1] = r3;
            }
            #pragma unroll
            for (int i = 0; i < 4; ++i)
                #pragma unroll
                for (int j = 0; j < 4; ++j)
                    mma_16816(acc[i][j], a[i], b[j]);
        }
        __syncthreads();   // all warps done reading buf before stage(p+2) overwrites it
    }

    // ---- epilogue: bias + relu; fp32 out + optional next-layer images ----
    #pragma unroll
    for (int i = 0; i < 4; ++i) {
        int rloc0 = wm + i * 16 + (lane >> 2);
        int r0 = m0 + rloc0;
        #pragma unroll
        for (int j = 0; j < 4; ++j) {
            int col = wn + j * 8 + (lane & 3) * 2;
            float bx = bias[col], by = bias[col + 1];
            float2 v0 = make_float2(acc[i][j][0] + bx, acc[i][j][1] + by);
            float2 v1 = make_float2(acc[i][j][2] + bx, acc[i][j][3] + by);
            if (relu) {
                v0.x = fmaxf(v0.x, 0.f); v0.y = fmaxf(v0.y, 0.f);
                v1.x = fmaxf(v1.x, 0.f); v1.y = fmaxf(v1.y, 0.f);
            }
            if (r0 < N_NODES)
                *reinterpret_cast<float2*>(out + (size_t)r0 * D + col) = v0;
            if (r0 + 8 < N_NODES)
                *reinterpret_cast<float2*>(out + (size_t)(r0 + 8) * D + col) = v1;
            if (write_img) {
                uint32_t obase = (uint32_t)tile * 32768u + (uint32_t)(col >> 6) * 16384u;
                uint32_t kb = (uint32_t)((col & 63) * 2);
                uint32_t hp, lp;
                if (r0 < N_NODES) {
                    split2(v0.x, v0.y, hp, lp);
                    uint32_t off = obase + swz((uint32_t)rloc0, kb);
                    *(uint32_t*)(oImgH + off) = hp;
                    *(uint32_t*)(oImgL + off) = lp;
                }
                if (r0 + 8 < N_NODES) {
                    split2(v1.x, v1.y, hp, lp);
                    uint32_t off = obase + swz((uint32_t)(rloc0 + 8), kb);
                    *(uint32_t*)(oImgH + off) = hp;
                    *(uint32_t*)(oImgL + off) = lp;
                }
            }
        }
    }
}

// ==================== launch ====================
extern "C" void kernel_launch(void* const* d_in, const int* in_sizes, int n_in,
                              void* d_out, int out_size) {
    const float* features = (const float*)d_in[0];
    const int* src = (const int*)d_in[1];
    const int* dst = (const int*)d_in[2];
    const float* Ws[3] = {(const float*)d_in[3], (const float*)d_in[6], (const float*)d_in[9]};
    const float* Wn[3] = {(const float*)d_in[4], (const float*)d_in[7], (const float*)d_in[10]};
    const float* bb[3] = {(const float*)d_in[5], (const float*)d_in[8], (const float*)d_in[11]};
    float* out = (float*)d_out;

    void *p_h0, *p_h1, *p_hist, *p_bimg, *p_imgA, *p_imgN;
    cudaGetSymbolAddress(&p_h0, g_hbuf0);
    cudaGetSymbolAddress(&p_h1, g_hbuf1);
    cudaGetSymbolAddress(&p_hist, g_hist);
    cudaGetSymbolAddress(&p_bimg, g_Bimg);
    cudaGetSymbolAddress(&p_imgA, g_imgA);
    cudaGetSymbolAddress(&p_imgN, g_imgN);

    char* bimg = (char*)p_bimg;
    auto wimg = [&](int mat) { return bimg + (size_t)mat * 65536; };
    const size_t ISZ = (size_t)NT * 32768;
    char* aimg = (char*)p_imgA;
    auto aimgp = [&](int set, int part) { return aimg + ((size_t)set * 2 + part) * ISZ; };
    char* nimg = (char*)p_imgN;

    const size_t smem_bytes = 2 * 32768 + 128;
    cudaFuncSetAttribute(gemm_hmma_kernel, cudaFuncAttributeMaxDynamicSharedMemorySize,
                         (int)smem_bytes);

    cudaMemsetAsync(p_hist, 0, N_NODES * sizeof(int));
    hist_kernel<<<(N_EDGES + 255) / 256, 256>>>(dst);
    convert_features<<<NT, 256>>>(features, aimgp(0, 0), aimgp(0, 1));
    prep_weights<<<48, 256>>>(Ws[0], Wn[0], Ws[1], Wn[1], Ws[2], Wn[2]);
    scan_local<<<SCAN_BLOCKS, 256>>>();
    scan_blocks<<<1, 256>>>();
    scan_apply<<<SCAN_BLOCKS, 256>>>();
    fill_kernel<<<(N_EDGES + 255) / 256, 256>>>(src, dst);

    const float* hin = features;
    float* bufs[3] = {(float*)p_h0, (float*)p_h1, out};
    for (int l = 0; l < 3; ++l) {
        int rset = l & 1;
        int wset = 1 - rset;
        aggregate_kernel<<<(N_NODES * 32 + 255) / 256, 256>>>(hin, nimg, nimg + ISZ);
        gemm_hmma_kernel<<<NT, 256, smem_bytes>>>(
            aimgp(rset, 0), aimgp(rset, 1), nimg, nimg + ISZ,
            wimg(l * 2 + 0), wimg(l * 2 + 1), bb[l], bufs[l],
            aimgp(wset, 0), aimgp(wset, 1), (l < 2) ? 1 : 0, (l < 2) ? 1 : 0);
        hin = bufs[l];
    }
}